// round 2
// baseline (speedup 1.0000x reference)
#include <cuda_runtime.h>

#define N_NODES 50000
#define E_EDGES 800000
#define NIN     128
#define HC      128
#define ED      44
#define NHEAD   4

// ----------------------------- scratch (static device globals) ---------------
__device__ float g_q   [N_NODES * HC];
__device__ float g_k   [N_NODES * HC];
__device__ float g_v   [N_NODES * HC];
__device__ float g_skip[N_NODES * HC];
__device__ float g_vj  [E_EDGES * HC];      // v[src] + e, per edge (410 MB)
__device__ float g_alpha[E_EDGES * NHEAD];  // pre-softmax logits
__device__ int   g_count[N_NODES];
__device__ int   g_cur  [N_NODES];
__device__ int   g_off  [N_NODES + 1];
__device__ int   g_elist[E_EDGES];
__device__ int   g_is64;                    // 1 if edge_index is int64

// ----------------------------- dtype detection -------------------------------
// Reads only the first 16384 32-bit words (safe under both dtypes: min buffer
// is 2*E int32 = 1.6M words). If int64 data: odd words are high words of
// values < 50000 -> all zero. If int32 data: odd words are random indices.
__global__ void detect_kernel(const int* __restrict__ w)
{
    __shared__ int s[256];
    int t = threadIdx.x;
    int acc = 0;
    for (int i = t; i < 8192; i += 256) acc |= w[2 * i + 1];
    s[t] = acc;
    __syncthreads();
    for (int step = 128; step > 0; step >>= 1) {
        if (t < step) s[t] |= s[t + step];
        __syncthreads();
    }
    if (t == 0) g_is64 = (s[0] == 0) ? 1 : 0;
}

__device__ __forceinline__ int ld_src(const void* ei, int e)
{
    return g_is64 ? (int)((const long long*)ei)[e]
                  : ((const int*)ei)[e];
}
__device__ __forceinline__ int ld_dst(const void* ei, int e)
{
    return g_is64 ? (int)((const long long*)ei)[E_EDGES + e]
                  : ((const int*)ei)[E_EDGES + e];
}

// ----------------------------- CSR build -------------------------------------
__global__ void zero_counts_kernel()
{
    int i = blockIdx.x * blockDim.x + threadIdx.x;
    if (i < N_NODES) g_count[i] = 0;
}

__global__ void count_kernel(const void* __restrict__ ei)
{
    int e = blockIdx.x * blockDim.x + threadIdx.x;   // grid sized exactly E
    int dst = ld_dst(ei, e);
    if (dst >= 0 && dst < N_NODES) atomicAdd(&g_count[dst], 1);
}

__global__ void scan_kernel()
{
    __shared__ int wsum[32];
    __shared__ int chunk_tot;
    const int t = threadIdx.x;           // 1024 threads
    const int lane = t & 31, wid = t >> 5;
    int run = 0;
    for (int base = 0; base < N_NODES; base += 1024) {
        int idx = base + t;
        int v = (idx < N_NODES) ? g_count[idx] : 0;
        int incl = v;
        #pragma unroll
        for (int s = 1; s < 32; s <<= 1) {
            int o = __shfl_up_sync(0xffffffffu, incl, s);
            if (lane >= s) incl += o;
        }
        if (lane == 31) wsum[wid] = incl;
        __syncthreads();
        if (wid == 0) {
            int wv = wsum[lane];
            int winc = wv;
            #pragma unroll
            for (int s = 1; s < 32; s <<= 1) {
                int o = __shfl_up_sync(0xffffffffu, winc, s);
                if (lane >= s) winc += o;
            }
            wsum[lane] = winc - wv;      // exclusive per-warp offset
        }
        __syncthreads();
        int excl = run + wsum[wid] + incl - v;
        if (idx < N_NODES) { g_off[idx] = excl; g_cur[idx] = excl; }
        if (t == 1023) chunk_tot = excl + v - run;
        __syncthreads();
        run += chunk_tot;
    }
    if (t == 0) g_off[N_NODES] = run;
}

__global__ void fill_kernel(const void* __restrict__ ei)
{
    int e = blockIdx.x * blockDim.x + threadIdx.x;   // grid sized exactly E
    int dst = ld_dst(ei, e);
    if (dst >= 0 && dst < N_NODES) {
        int pos = atomicAdd(&g_cur[dst], 1);
        g_elist[pos] = e;
    }
}

// ----------------------------- node projections ------------------------------
// Tile: 64 nodes x 128 cols, 256 threads, each thread 4 nodes x 8 cols.
__global__ void __launch_bounds__(256, 2)
node_proj_kernel(const float* __restrict__ x,
                 const float* __restrict__ Wq, const float* __restrict__ bq,
                 const float* __restrict__ Wk, const float* __restrict__ bk,
                 const float* __restrict__ Wv, const float* __restrict__ bv,
                 const float* __restrict__ Wsk, const float* __restrict__ bsk)
{
    extern __shared__ float sm[];
    float* sx = sm;              // 64*128
    float* sW = sm + 64 * 128;   // 128*128
    const int tid = threadIdx.x;
    const int n0 = blockIdx.x * 64;

    for (int i = tid * 4; i < 64 * 128; i += 256 * 4) {
        int r = i >> 7, c = i & 127;
        int node = n0 + r;
        float4 val = make_float4(0.f, 0.f, 0.f, 0.f);
        if (node < N_NODES) val = *(const float4*)(x + node * NIN + c);
        *(float4*)(sx + i) = val;
    }

    const float* Ws[4] = {Wq, Wk, Wv, Wsk};
    const float* Bs[4] = {bq, bk, bv, bsk};
    float* Os[4] = {g_q, g_k, g_v, g_skip};

    const int ty = tid >> 4;     // node group 0..15 -> nodes ty*4..+3
    const int tx = tid & 15;     // col group  0..15 -> cols tx*8..+7

    for (int p = 0; p < 4; ++p) {
        __syncthreads();   // protect sW (and sx on first pass)
        const float* W = Ws[p];
        for (int i = tid * 4; i < 128 * 128; i += 256 * 4)
            *(float4*)(sW + i) = *(const float4*)(W + i);
        __syncthreads();

        float acc[4][8];
        #pragma unroll
        for (int i = 0; i < 4; ++i)
            #pragma unroll
            for (int j = 0; j < 8; ++j) acc[i][j] = 0.f;

        #pragma unroll 4
        for (int k = 0; k < 128; ++k) {
            float4 b0 = *(float4*)(sW + k * 128 + tx * 8);
            float4 b1 = *(float4*)(sW + k * 128 + tx * 8 + 4);
            float bb[8] = {b0.x, b0.y, b0.z, b0.w, b1.x, b1.y, b1.z, b1.w};
            #pragma unroll
            for (int i = 0; i < 4; ++i) {
                float a = sx[(ty * 4 + i) * 128 + k];
                #pragma unroll
                for (int j = 0; j < 8; ++j)
                    acc[i][j] = fmaf(a, bb[j], acc[i][j]);
            }
        }

        float4 c0 = *(const float4*)(Bs[p] + tx * 8);
        float4 c1 = *(const float4*)(Bs[p] + tx * 8 + 4);
        float bias[8] = {c0.x, c0.y, c0.z, c0.w, c1.x, c1.y, c1.z, c1.w};
        float* O = Os[p];
        #pragma unroll
        for (int i = 0; i < 4; ++i) {
            int node = n0 + ty * 4 + i;
            if (node < N_NODES) {
                float4 o0 = make_float4(acc[i][0] + bias[0], acc[i][1] + bias[1],
                                        acc[i][2] + bias[2], acc[i][3] + bias[3]);
                float4 o1 = make_float4(acc[i][4] + bias[4], acc[i][5] + bias[5],
                                        acc[i][6] + bias[6], acc[i][7] + bias[7]);
                *(float4*)(O + node * HC + tx * 8)     = o0;
                *(float4*)(O + node * HC + tx * 8 + 4) = o1;
            }
        }
    }
}

// ----------------------------- fused edge kernel ------------------------------
// Phase 1: e = edge_attr @ We into registers (sA + sWe in smem).
// Phase 2 (after sync): acc tile written into smem REUSING the sA/sWe space,
// then per-warp alpha dot + v_j store. smem = 128*132 floats = 67.6 KB -> 3 CTAs/SM.
__global__ void __launch_bounds__(256, 3)
edge_kernel(const float* __restrict__ edge_attr,
            const void* __restrict__ ei,
            const float* __restrict__ We)
{
    extern __shared__ float sm[];
    float* sA  = sm;                      // 128 * 45 (padded)     [phase 1]
    float* sWe = sm + 128 * 45;           // 44 * 128              [phase 1]
    float* sE  = sm;                      // 128 * 132 (padded)    [phase 2]
    const int tid = threadIdx.x;
    const int e0 = blockIdx.x * 128;      // E divisible by 128

    for (int i = tid; i < 128 * ED; i += 256) {
        int r = i / ED, c = i - r * ED;
        sA[r * 45 + c] = edge_attr[(e0 + r) * ED + c];
    }
    for (int i = tid * 4; i < ED * 128; i += 256 * 4)
        *(float4*)(sWe + i) = *(const float4*)(We + i);
    __syncthreads();

    const int ty = tid >> 4;   // edge group: edges ty*8..+7
    const int tx = tid & 15;   // col group:  cols  tx*8..+7

    float acc[8][8];
    #pragma unroll
    for (int i = 0; i < 8; ++i)
        #pragma unroll
        for (int j = 0; j < 8; ++j) acc[i][j] = 0.f;

    #pragma unroll 4
    for (int k = 0; k < ED; ++k) {
        float4 b0 = *(float4*)(sWe + k * 128 + tx * 8);
        float4 b1 = *(float4*)(sWe + k * 128 + tx * 8 + 4);
        float bb[8] = {b0.x, b0.y, b0.z, b0.w, b1.x, b1.y, b1.z, b1.w};
        #pragma unroll
        for (int i = 0; i < 8; ++i) {
            float a = sA[(ty * 8 + i) * 45 + k];
            #pragma unroll
            for (int j = 0; j < 8; ++j)
                acc[i][j] = fmaf(a, bb[j], acc[i][j]);
        }
    }
    __syncthreads();   // everyone done reading sA/sWe before overwriting with sE

    #pragma unroll
    for (int i = 0; i < 8; ++i) {
        *(float4*)(sE + (ty * 8 + i) * 132 + tx * 8) =
            make_float4(acc[i][0], acc[i][1], acc[i][2], acc[i][3]);
        *(float4*)(sE + (ty * 8 + i) * 132 + tx * 8 + 4) =
            make_float4(acc[i][4], acc[i][5], acc[i][6], acc[i][7]);
    }
    __syncthreads();

    const int w = tid >> 5, l = tid & 31;
    for (int it = 0; it < 16; ++it) {
        int eloc = w * 16 + it;
        int e = e0 + eloc;
        int src = ld_src(ei, e);
        int dst = ld_dst(ei, e);
        src = min(max(src, 0), N_NODES - 1);
        dst = min(max(dst, 0), N_NODES - 1);
        float part[4], vj[4];
        #pragma unroll
        for (int j = 0; j < 4; ++j) {
            int col = l + 32 * j;                 // head j, channel l
            float ev = sE[eloc * 132 + col];
            float qv = g_q[dst * HC + col];
            float kv = g_k[src * HC + col];
            float vv = g_v[src * HC + col];
            part[j] = qv * (kv + ev);
            vj[j]   = vv + ev;
        }
        #pragma unroll
        for (int s = 16; s > 0; s >>= 1) {
            #pragma unroll
            for (int j = 0; j < 4; ++j)
                part[j] += __shfl_xor_sync(0xffffffffu, part[j], s);
        }
        if (l == 0) {
            const float isc = 0.17677669529663689f;   // 1/sqrt(32)
            float4 al = make_float4(part[0] * isc, part[1] * isc,
                                    part[2] * isc, part[3] * isc);
            *(float4*)(g_alpha + e * 4) = al;
        }
        #pragma unroll
        for (int j = 0; j < 4; ++j)
            g_vj[e * HC + l + 32 * j] = vj[j];
    }
}

// ----------------------------- aggregation (online softmax) -------------------
// One warp per (node, head); lane = channel. No float atomics.
__global__ void agg_kernel(float* __restrict__ out)
{
    int gw = (blockIdx.x * blockDim.x + threadIdx.x) >> 5;   // exactly N*H warps
    int l = threadIdx.x & 31;
    int n = gw >> 2, h = gw & 3;
    int beg = g_off[n], end = g_off[n + 1];
    int base = h * 32 + l;
    float m = -1e30f, den = 0.f, acc = 0.f;
    for (int i = beg; i < end; ++i) {
        int e = g_elist[i];
        float alpha = g_alpha[e * 4 + h];
        float vj = g_vj[e * HC + base];
        float nm = fmaxf(m, alpha);
        float sc = __expf(m - nm);
        float wt = __expf(alpha - nm);
        den = den * sc + wt;
        acc = acc * sc + wt * vj;
        m = nm;
    }
    int o = n * HC + base;
    out[o] = acc / (den + 1e-16f) + g_skip[o];
}

// ----------------------------- launch -----------------------------------------
extern "C" void kernel_launch(void* const* d_in, const int* in_sizes, int n_in,
                              void* d_out, int out_size)
{
    const float* x   = (const float*)d_in[0];
    const void*  ei  = d_in[1];
    const float* ea  = (const float*)d_in[2];
    const float* Wq  = (const float*)d_in[3];
    const float* bq  = (const float*)d_in[4];
    const float* Wk  = (const float*)d_in[5];
    const float* bk  = (const float*)d_in[6];
    const float* Wv  = (const float*)d_in[7];
    const float* bv  = (const float*)d_in[8];
    const float* We  = (const float*)d_in[9];
    const float* Wsk = (const float*)d_in[10];
    const float* bsk = (const float*)d_in[11];
    float* out = (float*)d_out;

    const int smem_node = (64 * 128 + 128 * 128) * 4;   // 96 KB
    const int smem_edge = (128 * 132) * 4;              // 67.6 KB (reused region)
    cudaFuncSetAttribute(node_proj_kernel,
                         cudaFuncAttributeMaxDynamicSharedMemorySize, smem_node);
    cudaFuncSetAttribute(edge_kernel,
                         cudaFuncAttributeMaxDynamicSharedMemorySize, smem_edge);

    detect_kernel<<<1, 256>>>((const int*)ei);
    zero_counts_kernel<<<(N_NODES + 255) / 256, 256>>>();
    count_kernel<<<E_EDGES / 256, 256>>>(ei);
    scan_kernel<<<1, 1024>>>();
    fill_kernel<<<E_EDGES / 256, 256>>>(ei);

    node_proj_kernel<<<(N_NODES + 63) / 64, 256, smem_node>>>(
        x, Wq, bq, Wk, bk, Wv, bv, Wsk, bsk);
    edge_kernel<<<E_EDGES / 128, 256, smem_edge>>>(ea, ei, We);
    agg_kernel<<<(N_NODES * NHEAD * 32) / 256, 256>>>(out);
}

// round 3
// speedup vs baseline: 2.1918x; 2.1918x over previous
#include <cuda_runtime.h>
#include <cuda_fp16.h>

#define N_NODES 50000
#define E_EDGES 800000
#define NIN     128
#define HC      128
#define ED      44
#define NHEAD   4
#define SCAN_B  196   // ceil(N_NODES/256)

// ----------------------------- scratch (static device globals) ---------------
__device__ float  g_q   [N_NODES * HC];
__device__ float  g_k   [N_NODES * HC];
__device__ float  g_v   [N_NODES * HC];
__device__ float  g_skip[N_NODES * HC];
__device__ __half g_vjh [E_EDGES * HC];      // v[src] + e, fp16 (205 MB)
__device__ float  g_alpha[E_EDGES * NHEAD];  // pre-softmax logits
__device__ int    g_count[N_NODES];
__device__ int    g_cur  [N_NODES];
__device__ int    g_off  [N_NODES + 1];
__device__ int    g_elist[E_EDGES];
__device__ int    g_bsum [SCAN_B];
__device__ int    g_boff [SCAN_B];
__device__ int    g_is64;                    // 1 if edge_index is int64

// ----------------------------- dtype detection -------------------------------
__global__ void detect_kernel(const int* __restrict__ w)
{
    __shared__ int s[256];
    int t = threadIdx.x;
    int acc = 0;
    for (int i = t; i < 8192; i += 256) acc |= w[2 * i + 1];
    s[t] = acc;
    __syncthreads();
    for (int step = 128; step > 0; step >>= 1) {
        if (t < step) s[t] |= s[t + step];
        __syncthreads();
    }
    if (t == 0) g_is64 = (s[0] == 0) ? 1 : 0;
}

__device__ __forceinline__ int ld_src(const void* ei, int e)
{
    return g_is64 ? (int)((const long long*)ei)[e] : ((const int*)ei)[e];
}
__device__ __forceinline__ int ld_dst(const void* ei, int e)
{
    return g_is64 ? (int)((const long long*)ei)[E_EDGES + e]
                  : ((const int*)ei)[E_EDGES + e];
}

// ----------------------------- CSR build -------------------------------------
__global__ void zero_counts_kernel()
{
    int i = blockIdx.x * blockDim.x + threadIdx.x;
    if (i < N_NODES) g_count[i] = 0;
}

__global__ void count_kernel(const void* __restrict__ ei)
{
    int e = blockIdx.x * blockDim.x + threadIdx.x;
    int dst = ld_dst(ei, e);
    if (dst >= 0 && dst < N_NODES) atomicAdd(&g_count[dst], 1);
}

// block-wide inclusive scan helper (256 threads)
__device__ __forceinline__ int block_incl_scan(int v, int* ws)
{
    const int lane = threadIdx.x & 31, wid = threadIdx.x >> 5;
    int incl = v;
    #pragma unroll
    for (int s = 1; s < 32; s <<= 1) {
        int o = __shfl_up_sync(0xffffffffu, incl, s);
        if (lane >= s) incl += o;
    }
    if (lane == 31) ws[wid] = incl;
    __syncthreads();
    if (wid == 0) {
        int wv = (lane < 8) ? ws[lane] : 0;
        int wi = wv;
        #pragma unroll
        for (int s = 1; s < 8; s <<= 1) {
            int o = __shfl_up_sync(0xffffffffu, wi, s);
            if (lane >= s) wi += o;
        }
        if (lane < 8) ws[lane] = wi - wv;   // exclusive warp offsets
    }
    __syncthreads();
    return ws[wid] + incl;                  // block-inclusive
}

__global__ void scan1_kernel()   // per-block sums
{
    __shared__ int ws[8];
    int idx = blockIdx.x * 256 + threadIdx.x;
    int v = (idx < N_NODES) ? g_count[idx] : 0;
    int incl = block_incl_scan(v, ws);
    if (threadIdx.x == 255) g_bsum[blockIdx.x] = incl;
}

__global__ void scan2_kernel()   // scan the 196 block sums
{
    __shared__ int ws[8];
    int t = threadIdx.x;
    int v = (t < SCAN_B) ? g_bsum[t] : 0;
    int incl = block_incl_scan(v, ws);
    if (t < SCAN_B) g_boff[t] = incl - v;
    if (t == SCAN_B - 1) g_off[N_NODES] = incl;
}

__global__ void scan3_kernel()   // final offsets
{
    __shared__ int ws[8];
    int idx = blockIdx.x * 256 + threadIdx.x;
    int v = (idx < N_NODES) ? g_count[idx] : 0;
    int incl = block_incl_scan(v, ws);
    if (idx < N_NODES) {
        int off = g_boff[blockIdx.x] + incl - v;
        g_off[idx] = off;
        g_cur[idx] = off;
    }
}

__global__ void fill_kernel(const void* __restrict__ ei)
{
    int e = blockIdx.x * blockDim.x + threadIdx.x;
    int dst = ld_dst(ei, e);
    if (dst >= 0 && dst < N_NODES) {
        int pos = atomicAdd(&g_cur[dst], 1);
        g_elist[pos] = e;
    }
}

// ----------------------------- node projections ------------------------------
// 128 nodes x 128 cols per block, 256 threads, 8x8 register tile.
// sx padded to 132 floats/row. smem = 130 KB -> 1 CTA/SM, 255-reg budget.
__global__ void __launch_bounds__(256, 1)
node_proj_kernel(const float* __restrict__ x,
                 const float* __restrict__ Wq, const float* __restrict__ bq,
                 const float* __restrict__ Wk, const float* __restrict__ bk,
                 const float* __restrict__ Wv, const float* __restrict__ bv,
                 const float* __restrict__ Wsk, const float* __restrict__ bsk)
{
    extern __shared__ float sm[];
    float* sx = sm;                 // 128 * 132
    float* sW = sm + 128 * 132;     // 128 * 128
    const int tid = threadIdx.x;
    const int n0 = blockIdx.x * 128;

    for (int i = tid * 4; i < 128 * 128; i += 256 * 4) {
        int r = i >> 7, c = i & 127;
        int node = n0 + r;
        float4 val = make_float4(0.f, 0.f, 0.f, 0.f);
        if (node < N_NODES) val = *(const float4*)(x + node * NIN + c);
        *(float4*)(sx + r * 132 + c) = val;
    }

    const float* Ws[4] = {Wq, Wk, Wv, Wsk};
    const float* Bs[4] = {bq, bk, bv, bsk};
    float* Os[4] = {g_q, g_k, g_v, g_skip};

    const int ty = tid >> 4;     // node group: nodes ty*8..+7
    const int tx = tid & 15;     // col group:  cols  tx*8..+7

    for (int p = 0; p < 4; ++p) {
        __syncthreads();
        const float* W = Ws[p];
        for (int i = tid * 4; i < 128 * 128; i += 256 * 4)
            *(float4*)(sW + i) = *(const float4*)(W + i);
        __syncthreads();

        float acc[8][8];
        #pragma unroll
        for (int i = 0; i < 8; ++i)
            #pragma unroll
            for (int j = 0; j < 8; ++j) acc[i][j] = 0.f;

        for (int k = 0; k < 128; k += 4) {
            float4 av[8];
            #pragma unroll
            for (int i = 0; i < 8; ++i)
                av[i] = *(float4*)(sx + (ty * 8 + i) * 132 + k);
            #pragma unroll
            for (int kk = 0; kk < 4; ++kk) {
                float4 b0 = *(float4*)(sW + (k + kk) * 128 + tx * 8);
                float4 b1 = *(float4*)(sW + (k + kk) * 128 + tx * 8 + 4);
                float bb[8] = {b0.x, b0.y, b0.z, b0.w, b1.x, b1.y, b1.z, b1.w};
                #pragma unroll
                for (int i = 0; i < 8; ++i) {
                    float a = (kk == 0) ? av[i].x : (kk == 1) ? av[i].y
                             : (kk == 2) ? av[i].z : av[i].w;
                    #pragma unroll
                    for (int j = 0; j < 8; ++j)
                        acc[i][j] = fmaf(a, bb[j], acc[i][j]);
                }
            }
        }

        float4 c0 = *(const float4*)(Bs[p] + tx * 8);
        float4 c1 = *(const float4*)(Bs[p] + tx * 8 + 4);
        float bias[8] = {c0.x, c0.y, c0.z, c0.w, c1.x, c1.y, c1.z, c1.w};
        float* O = Os[p];
        #pragma unroll
        for (int i = 0; i < 8; ++i) {
            int node = n0 + ty * 8 + i;
            if (node < N_NODES) {
                *(float4*)(O + node * HC + tx * 8) =
                    make_float4(acc[i][0] + bias[0], acc[i][1] + bias[1],
                                acc[i][2] + bias[2], acc[i][3] + bias[3]);
                *(float4*)(O + node * HC + tx * 8 + 4) =
                    make_float4(acc[i][4] + bias[4], acc[i][5] + bias[5],
                                acc[i][6] + bias[6], acc[i][7] + bias[7]);
            }
        }
    }
}

// ----------------------------- fused edge kernel ------------------------------
// Phase 1: e = edge_attr @ We (8x8 reg tile), sA (stride 48) + sWe in smem.
// Phase 2: e tile staged in smem (reusing phase-1 space), per-warp alpha dot
// + fp16 v_j store. smem = 67.6 KB. launch_bounds(256,2): 128-reg budget, no spill.
__global__ void __launch_bounds__(256, 2)
edge_kernel(const float* __restrict__ edge_attr,
            const void* __restrict__ ei,
            const float* __restrict__ We)
{
    extern __shared__ float sm[];
    float* sA  = sm;                      // 128 * 48   [phase 1]
    float* sWe = sm + 128 * 48;           // 44 * 128   [phase 1]
    float* sE  = sm;                      // 128 * 132  [phase 2]
    const int tid = threadIdx.x;
    const int e0 = blockIdx.x * 128;      // E divisible by 128

    for (int i = tid; i < 128 * ED; i += 256) {
        int r = i / ED, c = i - r * ED;
        sA[r * 48 + c] = edge_attr[(e0 + r) * ED + c];
    }
    for (int i = tid; i < 128; i += 256) {        // zero the k padding 44..47
        sA[i * 48 + 44] = 0.f; sA[i * 48 + 45] = 0.f;
        sA[i * 48 + 46] = 0.f; sA[i * 48 + 47] = 0.f;
    }
    for (int i = tid * 4; i < ED * 128; i += 256 * 4)
        *(float4*)(sWe + i) = *(const float4*)(We + i);
    __syncthreads();

    const int ty = tid >> 4;   // edge group: edges ty*8..+7
    const int tx = tid & 15;   // col group:  cols  tx*8..+7

    float acc[8][8];
    #pragma unroll
    for (int i = 0; i < 8; ++i)
        #pragma unroll
        for (int j = 0; j < 8; ++j) acc[i][j] = 0.f;

    for (int k = 0; k < ED; k += 4) {
        float4 av[8];
        #pragma unroll
        for (int i = 0; i < 8; ++i)
            av[i] = *(float4*)(sA + (ty * 8 + i) * 48 + k);
        #pragma unroll
        for (int kk = 0; kk < 4; ++kk) {
            if (k + kk >= ED) break;
            float4 b0 = *(float4*)(sWe + (k + kk) * 128 + tx * 8);
            float4 b1 = *(float4*)(sWe + (k + kk) * 128 + tx * 8 + 4);
            float bb[8] = {b0.x, b0.y, b0.z, b0.w, b1.x, b1.y, b1.z, b1.w};
            #pragma unroll
            for (int i = 0; i < 8; ++i) {
                float a = (kk == 0) ? av[i].x : (kk == 1) ? av[i].y
                         : (kk == 2) ? av[i].z : av[i].w;
                #pragma unroll
                for (int j = 0; j < 8; ++j)
                    acc[i][j] = fmaf(a, bb[j], acc[i][j]);
            }
        }
    }
    __syncthreads();   // done reading sA/sWe; sE overwrites them

    #pragma unroll
    for (int i = 0; i < 8; ++i) {
        *(float4*)(sE + (ty * 8 + i) * 132 + tx * 8) =
            make_float4(acc[i][0], acc[i][1], acc[i][2], acc[i][3]);
        *(float4*)(sE + (ty * 8 + i) * 132 + tx * 8 + 4) =
            make_float4(acc[i][4], acc[i][5], acc[i][6], acc[i][7]);
    }
    __syncthreads();

    const int w = tid >> 5, l = tid & 31;
    for (int it = 0; it < 16; ++it) {
        int eloc = w * 16 + it;
        int e = e0 + eloc;
        int src = ld_src(ei, e);
        int dst = ld_dst(ei, e);
        src = min(max(src, 0), N_NODES - 1);
        dst = min(max(dst, 0), N_NODES - 1);
        float part[4], vj[4];
        #pragma unroll
        for (int j = 0; j < 4; ++j) {
            int col = l + 32 * j;                 // head j, channel l
            float ev = sE[eloc * 132 + col];
            float qv = g_q[dst * HC + col];
            float kv = g_k[src * HC + col];
            float vv = g_v[src * HC + col];
            part[j] = qv * (kv + ev);
            vj[j]   = vv + ev;
        }
        #pragma unroll
        for (int s = 16; s > 0; s >>= 1) {
            #pragma unroll
            for (int j = 0; j < 4; ++j)
                part[j] += __shfl_xor_sync(0xffffffffu, part[j], s);
        }
        if (l == 0) {
            const float isc = 0.17677669529663689f;   // 1/sqrt(32)
            *(float4*)(g_alpha + e * 4) =
                make_float4(part[0] * isc, part[1] * isc,
                            part[2] * isc, part[3] * isc);
        }
        #pragma unroll
        for (int j = 0; j < 4; ++j)
            g_vjh[e * HC + l + 32 * j] = __float2half(vj[j]);
    }
}

// ----------------------------- aggregation (online softmax) -------------------
// One warp per node, all 4 heads per lane. No float atomics.
__global__ void agg_kernel(float* __restrict__ out)
{
    int n = (blockIdx.x * blockDim.x + threadIdx.x) >> 5;   // exactly N warps
    int l = threadIdx.x & 31;
    int beg = g_off[n], end = g_off[n + 1];
    float m[4], den[4], acc[4];
    #pragma unroll
    for (int j = 0; j < 4; ++j) { m[j] = -1e30f; den[j] = 0.f; acc[j] = 0.f; }
    for (int i = beg; i < end; ++i) {
        int e = g_elist[i];
        float4 al = *(const float4*)(g_alpha + e * 4);
        float a4[4] = {al.x, al.y, al.z, al.w};
        #pragma unroll
        for (int j = 0; j < 4; ++j) {
            float vj = __half2float(g_vjh[e * HC + 32 * j + l]);
            float nm = fmaxf(m[j], a4[j]);
            float sc = __expf(m[j] - nm);
            float wt = __expf(a4[j] - nm);
            den[j] = den[j] * sc + wt;
            acc[j] = acc[j] * sc + wt * vj;
            m[j] = nm;
        }
    }
    #pragma unroll
    for (int j = 0; j < 4; ++j) {
        int o = n * HC + 32 * j + l;
        out[o] = acc[j] / (den[j] + 1e-16f) + g_skip[o];
    }
}

// ----------------------------- launch -----------------------------------------
extern "C" void kernel_launch(void* const* d_in, const int* in_sizes, int n_in,
                              void* d_out, int out_size)
{
    const float* x   = (const float*)d_in[0];
    const void*  ei  = d_in[1];
    const float* ea  = (const float*)d_in[2];
    const float* Wq  = (const float*)d_in[3];
    const float* bq  = (const float*)d_in[4];
    const float* Wk  = (const float*)d_in[5];
    const float* bk  = (const float*)d_in[6];
    const float* Wv  = (const float*)d_in[7];
    const float* bv  = (const float*)d_in[8];
    const float* We  = (const float*)d_in[9];
    const float* Wsk = (const float*)d_in[10];
    const float* bsk = (const float*)d_in[11];
    float* out = (float*)d_out;

    const int smem_node = (128 * 132 + 128 * 128) * 4;   // 130 KB
    const int smem_edge = (128 * 132) * 4;               // 67.6 KB
    cudaFuncSetAttribute(node_proj_kernel,
                         cudaFuncAttributeMaxDynamicSharedMemorySize, smem_node);
    cudaFuncSetAttribute(edge_kernel,
                         cudaFuncAttributeMaxDynamicSharedMemorySize, smem_edge);

    detect_kernel<<<1, 256>>>((const int*)ei);
    zero_counts_kernel<<<(N_NODES + 255) / 256, 256>>>();
    count_kernel<<<E_EDGES / 256, 256>>>(ei);
    scan1_kernel<<<SCAN_B, 256>>>();
    scan2_kernel<<<1, 256>>>();
    scan3_kernel<<<SCAN_B, 256>>>();
    fill_kernel<<<E_EDGES / 256, 256>>>(ei);

    node_proj_kernel<<<(N_NODES + 127) / 128, 256, smem_node>>>(
        x, Wq, bq, Wk, bk, Wv, bv, Wsk, bsk);
    edge_kernel<<<E_EDGES / 128, 256, smem_edge>>>(ea, ei, We);
    agg_kernel<<<(N_NODES * 32) / 256, 256>>>(out);
}

// round 4
// speedup vs baseline: 2.2710x; 1.0362x over previous
#include <cuda_runtime.h>
#include <cuda_fp16.h>

#define N_NODES 50000
#define E_EDGES 800000
#define NIN     128
#define HC      128
#define ED      44
#define NHEAD   4
#define SCAN_B  196   // ceil(N_NODES/256)

typedef unsigned long long u64;

// ----------------------------- scratch (static device globals) ---------------
__device__ float  g_q   [N_NODES * HC];
__device__ float  g_k   [N_NODES * HC];
__device__ float  g_v   [N_NODES * HC];
__device__ float  g_skip[N_NODES * HC];
__device__ __half g_vjh [E_EDGES * HC];      // v[src]+e, fp16, CSR-ordered
__device__ float  g_alpha[E_EDGES * NHEAD];  // logits, CSR-ordered
__device__ int    g_count[N_NODES];
__device__ int    g_cur  [N_NODES];
__device__ int    g_off  [N_NODES + 1];
__device__ int    g_pos  [E_EDGES];          // CSR slot of each edge
__device__ int    g_bsum [SCAN_B];
__device__ int    g_boff [SCAN_B];
__device__ int    g_is64;

// ----------------------------- packed f32x2 helpers ---------------------------
__device__ __forceinline__ u64 pk2(float lo, float hi)
{
    u64 r; asm("mov.b64 %0, {%1, %2};" : "=l"(r) : "f"(lo), "f"(hi)); return r;
}
__device__ __forceinline__ void upk2(float& lo, float& hi, u64 v)
{
    asm("mov.b64 {%0, %1}, %2;" : "=f"(lo), "=f"(hi) : "l"(v));
}
__device__ __forceinline__ void ffma2(u64& d, u64 a, u64 b)
{
    asm("fma.rn.f32x2 %0, %1, %2, %3;" : "=l"(d) : "l"(a), "l"(b), "l"(d));
}

// ----------------------------- dtype detection -------------------------------
__global__ void detect_kernel(const int* __restrict__ w)
{
    __shared__ int s[256];
    int t = threadIdx.x;
    int acc = 0;
    for (int i = t; i < 8192; i += 256) acc |= w[2 * i + 1];
    s[t] = acc;
    __syncthreads();
    for (int step = 128; step > 0; step >>= 1) {
        if (t < step) s[t] |= s[t + step];
        __syncthreads();
    }
    if (t == 0) g_is64 = (s[0] == 0) ? 1 : 0;
}

__device__ __forceinline__ int ld_src(const void* ei, int e)
{
    return g_is64 ? (int)((const long long*)ei)[e] : ((const int*)ei)[e];
}
__device__ __forceinline__ int ld_dst(const void* ei, int e)
{
    return g_is64 ? (int)((const long long*)ei)[E_EDGES + e]
                  : ((const int*)ei)[E_EDGES + e];
}

// ----------------------------- CSR build -------------------------------------
__global__ void zero_counts_kernel()
{
    int i = blockIdx.x * blockDim.x + threadIdx.x;
    if (i < N_NODES) g_count[i] = 0;
}

__global__ void count_kernel(const void* __restrict__ ei)
{
    int e = blockIdx.x * blockDim.x + threadIdx.x;
    int dst = ld_dst(ei, e);
    if (dst >= 0 && dst < N_NODES) atomicAdd(&g_count[dst], 1);
}

__device__ __forceinline__ int block_incl_scan(int v, int* ws)
{
    const int lane = threadIdx.x & 31, wid = threadIdx.x >> 5;
    int incl = v;
    #pragma unroll
    for (int s = 1; s < 32; s <<= 1) {
        int o = __shfl_up_sync(0xffffffffu, incl, s);
        if (lane >= s) incl += o;
    }
    if (lane == 31) ws[wid] = incl;
    __syncthreads();
    if (wid == 0) {
        int wv = (lane < 8) ? ws[lane] : 0;
        int wi = wv;
        #pragma unroll
        for (int s = 1; s < 8; s <<= 1) {
            int o = __shfl_up_sync(0xffffffffu, wi, s);
            if (lane >= s) wi += o;
        }
        if (lane < 8) ws[lane] = wi - wv;
    }
    __syncthreads();
    return ws[wid] + incl;
}

__global__ void scan1_kernel()
{
    __shared__ int ws[8];
    int idx = blockIdx.x * 256 + threadIdx.x;
    int v = (idx < N_NODES) ? g_count[idx] : 0;
    int incl = block_incl_scan(v, ws);
    if (threadIdx.x == 255) g_bsum[blockIdx.x] = incl;
}

__global__ void scan2_kernel()
{
    __shared__ int ws[8];
    int t = threadIdx.x;
    int v = (t < SCAN_B) ? g_bsum[t] : 0;
    int incl = block_incl_scan(v, ws);
    if (t < SCAN_B) g_boff[t] = incl - v;
    if (t == SCAN_B - 1) g_off[N_NODES] = incl;
}

__global__ void scan3_kernel()
{
    __shared__ int ws[8];
    int idx = blockIdx.x * 256 + threadIdx.x;
    int v = (idx < N_NODES) ? g_count[idx] : 0;
    int incl = block_incl_scan(v, ws);
    if (idx < N_NODES) {
        int off = g_boff[blockIdx.x] + incl - v;
        g_off[idx] = off;
        g_cur[idx] = off;
    }
}

__global__ void fill_kernel(const void* __restrict__ ei)
{
    int e = blockIdx.x * blockDim.x + threadIdx.x;
    int dst = ld_dst(ei, e);
    int pos = 0;
    if (dst >= 0 && dst < N_NODES) pos = atomicAdd(&g_cur[dst], 1);
    g_pos[e] = pos;
}

// ----------------------------- node projections ------------------------------
// 128 nodes x 128 cols per block, 256 threads, 8x8 tile via packed f32x2 FMA.
__global__ void __launch_bounds__(256, 1)
node_proj_kernel(const float* __restrict__ x,
                 const float* __restrict__ Wq, const float* __restrict__ bq,
                 const float* __restrict__ Wk, const float* __restrict__ bk,
                 const float* __restrict__ Wv, const float* __restrict__ bv,
                 const float* __restrict__ Wsk, const float* __restrict__ bsk)
{
    extern __shared__ float sm[];
    float* sx = sm;                 // 128 * 132
    float* sW = sm + 128 * 132;     // 128 * 128
    const int tid = threadIdx.x;
    const int n0 = blockIdx.x * 128;

    for (int i = tid * 4; i < 128 * 128; i += 256 * 4) {
        int r = i >> 7, c = i & 127;
        int node = n0 + r;
        float4 val = make_float4(0.f, 0.f, 0.f, 0.f);
        if (node < N_NODES) val = *(const float4*)(x + node * NIN + c);
        *(float4*)(sx + r * 132 + c) = val;
    }

    const float* Ws[4] = {Wq, Wk, Wv, Wsk};
    const float* Bs[4] = {bq, bk, bv, bsk};
    float* Os[4] = {g_q, g_k, g_v, g_skip};

    const int ty = tid >> 4;     // nodes ty*8..+7
    const int tx = tid & 15;     // cols  tx*8..+7

    for (int p = 0; p < 4; ++p) {
        __syncthreads();
        const float* W = Ws[p];
        for (int i = tid * 4; i < 128 * 128; i += 256 * 4)
            *(float4*)(sW + i) = *(const float4*)(W + i);
        __syncthreads();

        u64 acc2[8][4];
        #pragma unroll
        for (int i = 0; i < 8; ++i)
            #pragma unroll
            for (int j = 0; j < 4; ++j) acc2[i][j] = 0ull;

        for (int k = 0; k < 128; k += 4) {
            float4 av[8];
            #pragma unroll
            for (int i = 0; i < 8; ++i)
                av[i] = *(float4*)(sx + (ty * 8 + i) * 132 + k);
            #pragma unroll
            for (int kk = 0; kk < 4; ++kk) {
                float4 b0 = *(float4*)(sW + (k + kk) * 128 + tx * 8);
                float4 b1 = *(float4*)(sW + (k + kk) * 128 + tx * 8 + 4);
                u64 bp[4] = {pk2(b0.x, b0.y), pk2(b0.z, b0.w),
                             pk2(b1.x, b1.y), pk2(b1.z, b1.w)};
                #pragma unroll
                for (int i = 0; i < 8; ++i) {
                    float a = (kk == 0) ? av[i].x : (kk == 1) ? av[i].y
                             : (kk == 2) ? av[i].z : av[i].w;
                    u64 ap = pk2(a, a);
                    #pragma unroll
                    for (int j = 0; j < 4; ++j) ffma2(acc2[i][j], ap, bp[j]);
                }
            }
        }

        float4 c0 = *(const float4*)(Bs[p] + tx * 8);
        float4 c1 = *(const float4*)(Bs[p] + tx * 8 + 4);
        float bias[8] = {c0.x, c0.y, c0.z, c0.w, c1.x, c1.y, c1.z, c1.w};
        float* O = Os[p];
        #pragma unroll
        for (int i = 0; i < 8; ++i) {
            int node = n0 + ty * 8 + i;
            if (node < N_NODES) {
                float a0, a1, a2, a3, a4, a5, a6, a7;
                upk2(a0, a1, acc2[i][0]); upk2(a2, a3, acc2[i][1]);
                upk2(a4, a5, acc2[i][2]); upk2(a6, a7, acc2[i][3]);
                *(float4*)(O + node * HC + tx * 8) =
                    make_float4(a0 + bias[0], a1 + bias[1], a2 + bias[2], a3 + bias[3]);
                *(float4*)(O + node * HC + tx * 8 + 4) =
                    make_float4(a4 + bias[4], a5 + bias[5], a6 + bias[6], a7 + bias[7]);
            }
        }
    }
}

// ----------------------------- fused edge kernel ------------------------------
__global__ void __launch_bounds__(256, 2)
edge_kernel(const float* __restrict__ edge_attr,
            const void* __restrict__ ei,
            const float* __restrict__ We)
{
    extern __shared__ float sm[];
    float* sA  = sm;                      // 128 * 48   [phase 1]
    float* sWe = sm + 128 * 48;           // 44 * 128   [phase 1]
    float* sE  = sm;                      // 128 * 132  [phase 2]
    const int tid = threadIdx.x;
    const int e0 = blockIdx.x * 128;      // E divisible by 128

    for (int i = tid; i < 128 * ED; i += 256) {
        int r = i / ED, c = i - r * ED;
        sA[r * 48 + c] = edge_attr[(e0 + r) * ED + c];
    }
    for (int i = tid; i < 128; i += 256) {
        sA[i * 48 + 44] = 0.f; sA[i * 48 + 45] = 0.f;
        sA[i * 48 + 46] = 0.f; sA[i * 48 + 47] = 0.f;
    }
    for (int i = tid * 4; i < ED * 128; i += 256 * 4)
        *(float4*)(sWe + i) = *(const float4*)(We + i);
    __syncthreads();

    const int ty = tid >> 4;   // edges ty*8..+7
    const int tx = tid & 15;   // cols  tx*8..+7

    u64 acc2[8][4];
    #pragma unroll
    for (int i = 0; i < 8; ++i)
        #pragma unroll
        for (int j = 0; j < 4; ++j) acc2[i][j] = 0ull;

    for (int k = 0; k < ED; k += 4) {          // 44 = 11 * 4, exact
        float4 av[8];
        #pragma unroll
        for (int i = 0; i < 8; ++i)
            av[i] = *(float4*)(sA + (ty * 8 + i) * 48 + k);
        #pragma unroll
        for (int kk = 0; kk < 4; ++kk) {
            float4 b0 = *(float4*)(sWe + (k + kk) * 128 + tx * 8);
            float4 b1 = *(float4*)(sWe + (k + kk) * 128 + tx * 8 + 4);
            u64 bp[4] = {pk2(b0.x, b0.y), pk2(b0.z, b0.w),
                         pk2(b1.x, b1.y), pk2(b1.z, b1.w)};
            #pragma unroll
            for (int i = 0; i < 8; ++i) {
                float a = (kk == 0) ? av[i].x : (kk == 1) ? av[i].y
                         : (kk == 2) ? av[i].z : av[i].w;
                u64 ap = pk2(a, a);
                #pragma unroll
                for (int j = 0; j < 4; ++j) ffma2(acc2[i][j], ap, bp[j]);
            }
        }
    }
    __syncthreads();   // done reading sA/sWe; sE overwrites them

    #pragma unroll
    for (int i = 0; i < 8; ++i) {
        float a0, a1, a2, a3, a4, a5, a6, a7;
        upk2(a0, a1, acc2[i][0]); upk2(a2, a3, acc2[i][1]);
        upk2(a4, a5, acc2[i][2]); upk2(a6, a7, acc2[i][3]);
        *(float4*)(sE + (ty * 8 + i) * 132 + tx * 8)     = make_float4(a0, a1, a2, a3);
        *(float4*)(sE + (ty * 8 + i) * 132 + tx * 8 + 4) = make_float4(a4, a5, a6, a7);
    }
    __syncthreads();

    const int w = tid >> 5, l = tid & 31;
    for (int it = 0; it < 16; ++it) {
        int eloc = w * 16 + it;
        int e = e0 + eloc;
        int src = ld_src(ei, e);
        int dst = ld_dst(ei, e);
        src = min(max(src, 0), N_NODES - 1);
        dst = min(max(dst, 0), N_NODES - 1);
        int pos = g_pos[e];
        float part[4], vj[4];
        #pragma unroll
        for (int j = 0; j < 4; ++j) {
            int col = l + 32 * j;
            float ev = sE[eloc * 132 + col];
            float qv = g_q[dst * HC + col];
            float kv = g_k[src * HC + col];
            float vv = g_v[src * HC + col];
            part[j] = qv * (kv + ev);
            vj[j]   = vv + ev;
        }
        #pragma unroll
        for (int s = 16; s > 0; s >>= 1) {
            #pragma unroll
            for (int j = 0; j < 4; ++j)
                part[j] += __shfl_xor_sync(0xffffffffu, part[j], s);
        }
        if (l == 0) {
            const float isc = 0.17677669529663689f;   // 1/sqrt(32)
            *(float4*)(g_alpha + pos * 4) =
                make_float4(part[0] * isc, part[1] * isc,
                            part[2] * isc, part[3] * isc);
        }
        #pragma unroll
        for (int j = 0; j < 4; ++j)
            g_vjh[pos * HC + l + 32 * j] = __float2half(vj[j]);
    }
}

// ----------------------------- aggregation (online softmax) -------------------
// One warp per node; CSR-ordered alpha/vjh -> fully sequential streaming.
__global__ void agg_kernel(float* __restrict__ out)
{
    int n = (blockIdx.x * blockDim.x + threadIdx.x) >> 5;   // exactly N warps
    int l = threadIdx.x & 31;
    int beg = g_off[n], end = g_off[n + 1];
    float m[4], den[4], acc[4];
    #pragma unroll
    for (int j = 0; j < 4; ++j) { m[j] = -1e30f; den[j] = 0.f; acc[j] = 0.f; }
    for (int i = beg; i < end; ++i) {
        float4 al = *(const float4*)(g_alpha + i * 4);
        float a4[4] = {al.x, al.y, al.z, al.w};
        #pragma unroll
        for (int j = 0; j < 4; ++j) {
            float vj = __half2float(g_vjh[i * HC + 32 * j + l]);
            float nm = fmaxf(m[j], a4[j]);
            float sc = __expf(m[j] - nm);
            float wt = __expf(a4[j] - nm);
            den[j] = den[j] * sc + wt;
            acc[j] = acc[j] * sc + wt * vj;
            m[j] = nm;
        }
    }
    #pragma unroll
    for (int j = 0; j < 4; ++j) {
        int o = n * HC + 32 * j + l;
        out[o] = acc[j] / (den[j] + 1e-16f) + g_skip[o];
    }
}

// ----------------------------- launch -----------------------------------------
extern "C" void kernel_launch(void* const* d_in, const int* in_sizes, int n_in,
                              void* d_out, int out_size)
{
    const float* x   = (const float*)d_in[0];
    const void*  ei  = d_in[1];
    const float* ea  = (const float*)d_in[2];
    const float* Wq  = (const float*)d_in[3];
    const float* bq  = (const float*)d_in[4];
    const float* Wk  = (const float*)d_in[5];
    const float* bk  = (const float*)d_in[6];
    const float* Wv  = (const float*)d_in[7];
    const float* bv  = (const float*)d_in[8];
    const float* We  = (const float*)d_in[9];
    const float* Wsk = (const float*)d_in[10];
    const float* bsk = (const float*)d_in[11];
    float* out = (float*)d_out;

    const int smem_node = (128 * 132 + 128 * 128) * 4;   // 130 KB
    const int smem_edge = (128 * 132) * 4;               // 67.6 KB
    cudaFuncSetAttribute(node_proj_kernel,
                         cudaFuncAttributeMaxDynamicSharedMemorySize, smem_node);
    cudaFuncSetAttribute(edge_kernel,
                         cudaFuncAttributeMaxDynamicSharedMemorySize, smem_edge);

    detect_kernel<<<1, 256>>>((const int*)ei);
    zero_counts_kernel<<<(N_NODES + 255) / 256, 256>>>();
    count_kernel<<<E_EDGES / 256, 256>>>(ei);
    scan1_kernel<<<SCAN_B, 256>>>();
    scan2_kernel<<<1, 256>>>();
    scan3_kernel<<<SCAN_B, 256>>>();
    fill_kernel<<<E_EDGES / 256, 256>>>(ei);

    node_proj_kernel<<<(N_NODES + 127) / 128, 256, smem_node>>>(
        x, Wq, bq, Wk, bk, Wv, bv, Wsk, bsk);
    edge_kernel<<<E_EDGES / 128, 256, smem_edge>>>(ea, ei, We);
    agg_kernel<<<(N_NODES * 32) / 256, 256>>>(out);
}

// round 5
// speedup vs baseline: 2.7091x; 1.1929x over previous
#include <cuda_runtime.h>
#include <cuda_fp16.h>

#define N_NODES 50000
#define E_EDGES 800000
#define NIN     128
#define HC      128
#define ED      44
#define NHEAD   4
#define SCAN_B  196   // ceil(N_NODES/256)

typedef unsigned long long u64;

// ----------------------------- scratch (static device globals) ---------------
__device__ __half g_qh  [N_NODES * HC];
__device__ __half g_kh  [N_NODES * HC];
__device__ __half g_vh  [N_NODES * HC];
__device__ float  g_skip[N_NODES * HC];
__device__ __half g_vjh [E_EDGES * HC];      // v[src]+e, fp16, CSR-ordered
__device__ float  g_alpha[E_EDGES * NHEAD];  // logits, CSR-ordered
__device__ int    g_count[N_NODES];
__device__ int    g_cur  [N_NODES];
__device__ int    g_off  [N_NODES + 1];
__device__ int    g_pos  [E_EDGES];          // CSR slot of each edge
__device__ int    g_bsum [SCAN_B];
__device__ int    g_boff [SCAN_B];
__device__ int    g_is64;

// ----------------------------- packed f32x2 helpers ---------------------------
__device__ __forceinline__ u64 pk2(float lo, float hi)
{
    u64 r; asm("mov.b64 %0, {%1, %2};" : "=l"(r) : "f"(lo), "f"(hi)); return r;
}
__device__ __forceinline__ void upk2(float& lo, float& hi, u64 v)
{
    asm("mov.b64 {%0, %1}, %2;" : "=f"(lo), "=f"(hi) : "l"(v));
}
__device__ __forceinline__ void ffma2(u64& d, u64 a, u64 b)
{
    asm("fma.rn.f32x2 %0, %1, %2, %3;" : "=l"(d) : "l"(a), "l"(b), "l"(d));
}

// ----------------------------- dtype detection -------------------------------
__global__ void detect_kernel(const int* __restrict__ w)
{
    __shared__ int s[256];
    int t = threadIdx.x;
    int acc = 0;
    for (int i = t; i < 8192; i += 256) acc |= w[2 * i + 1];
    s[t] = acc;
    __syncthreads();
    for (int step = 128; step > 0; step >>= 1) {
        if (t < step) s[t] |= s[t + step];
        __syncthreads();
    }
    if (t == 0) g_is64 = (s[0] == 0) ? 1 : 0;
}

__device__ __forceinline__ int ld_src(const void* ei, int e)
{
    return g_is64 ? (int)((const long long*)ei)[e] : ((const int*)ei)[e];
}
__device__ __forceinline__ int ld_dst(const void* ei, int e)
{
    return g_is64 ? (int)((const long long*)ei)[E_EDGES + e]
                  : ((const int*)ei)[E_EDGES + e];
}

// ----------------------------- CSR build -------------------------------------
__global__ void zero_counts_kernel()
{
    int i = blockIdx.x * blockDim.x + threadIdx.x;
    if (i < N_NODES) g_count[i] = 0;
}

__global__ void count_kernel(const void* __restrict__ ei)
{
    int e = blockIdx.x * blockDim.x + threadIdx.x;
    int dst = ld_dst(ei, e);
    if (dst >= 0 && dst < N_NODES) atomicAdd(&g_count[dst], 1);
}

__device__ __forceinline__ int block_incl_scan(int v, int* ws)
{
    const int lane = threadIdx.x & 31, wid = threadIdx.x >> 5;
    int incl = v;
    #pragma unroll
    for (int s = 1; s < 32; s <<= 1) {
        int o = __shfl_up_sync(0xffffffffu, incl, s);
        if (lane >= s) incl += o;
    }
    if (lane == 31) ws[wid] = incl;
    __syncthreads();
    if (wid == 0) {
        int wv = (lane < 8) ? ws[lane] : 0;
        int wi = wv;
        #pragma unroll
        for (int s = 1; s < 8; s <<= 1) {
            int o = __shfl_up_sync(0xffffffffu, wi, s);
            if (lane >= s) wi += o;
        }
        if (lane < 8) ws[lane] = wi - wv;
    }
    __syncthreads();
    return ws[wid] + incl;
}

__global__ void scan1_kernel()
{
    __shared__ int ws[8];
    int idx = blockIdx.x * 256 + threadIdx.x;
    int v = (idx < N_NODES) ? g_count[idx] : 0;
    int incl = block_incl_scan(v, ws);
    if (threadIdx.x == 255) g_bsum[blockIdx.x] = incl;
}

__global__ void scan2_kernel()
{
    __shared__ int ws[8];
    int t = threadIdx.x;
    int v = (t < SCAN_B) ? g_bsum[t] : 0;
    int incl = block_incl_scan(v, ws);
    if (t < SCAN_B) g_boff[t] = incl - v;
    if (t == SCAN_B - 1) g_off[N_NODES] = incl;
}

__global__ void scan3_kernel()
{
    __shared__ int ws[8];
    int idx = blockIdx.x * 256 + threadIdx.x;
    int v = (idx < N_NODES) ? g_count[idx] : 0;
    int incl = block_incl_scan(v, ws);
    if (idx < N_NODES) {
        int off = g_boff[blockIdx.x] + incl - v;
        g_off[idx] = off;
        g_cur[idx] = off;
    }
}

__global__ void fill_kernel(const void* __restrict__ ei)
{
    int e = blockIdx.x * blockDim.x + threadIdx.x;
    int dst = ld_dst(ei, e);
    int pos = 0;
    if (dst >= 0 && dst < N_NODES) pos = atomicAdd(&g_cur[dst], 1);
    g_pos[e] = pos;
}

// ----------------------------- node projections ------------------------------
// 128 nodes x 128 cols per block, 256 threads, 8x8 tile via packed f32x2 FMA.
// q/k/v written as fp16; skip as fp32.
__global__ void __launch_bounds__(256, 1)
node_proj_kernel(const float* __restrict__ x,
                 const float* __restrict__ Wq, const float* __restrict__ bq,
                 const float* __restrict__ Wk, const float* __restrict__ bk,
                 const float* __restrict__ Wv, const float* __restrict__ bv,
                 const float* __restrict__ Wsk, const float* __restrict__ bsk)
{
    extern __shared__ float sm[];
    float* sx = sm;                 // 128 * 132
    float* sW = sm + 128 * 132;     // 128 * 128
    const int tid = threadIdx.x;
    const int n0 = blockIdx.x * 128;

    for (int i = tid * 4; i < 128 * 128; i += 256 * 4) {
        int r = i >> 7, c = i & 127;
        int node = n0 + r;
        float4 val = make_float4(0.f, 0.f, 0.f, 0.f);
        if (node < N_NODES) val = *(const float4*)(x + node * NIN + c);
        *(float4*)(sx + r * 132 + c) = val;
    }

    const float* Ws[4] = {Wq, Wk, Wv, Wsk};
    const float* Bs[4] = {bq, bk, bv, bsk};

    const int ty = tid >> 4;     // nodes ty*8..+7
    const int tx = tid & 15;     // cols  tx*8..+7

    for (int p = 0; p < 4; ++p) {
        __syncthreads();
        const float* W = Ws[p];
        for (int i = tid * 4; i < 128 * 128; i += 256 * 4)
            *(float4*)(sW + i) = *(const float4*)(W + i);
        __syncthreads();

        u64 acc2[8][4];
        #pragma unroll
        for (int i = 0; i < 8; ++i)
            #pragma unroll
            for (int j = 0; j < 4; ++j) acc2[i][j] = 0ull;

        for (int k = 0; k < 128; k += 4) {
            float4 av[8];
            #pragma unroll
            for (int i = 0; i < 8; ++i)
                av[i] = *(float4*)(sx + (ty * 8 + i) * 132 + k);
            #pragma unroll
            for (int kk = 0; kk < 4; ++kk) {
                float4 b0 = *(float4*)(sW + (k + kk) * 128 + tx * 8);
                float4 b1 = *(float4*)(sW + (k + kk) * 128 + tx * 8 + 4);
                u64 bp[4] = {pk2(b0.x, b0.y), pk2(b0.z, b0.w),
                             pk2(b1.x, b1.y), pk2(b1.z, b1.w)};
                #pragma unroll
                for (int i = 0; i < 8; ++i) {
                    float a = (kk == 0) ? av[i].x : (kk == 1) ? av[i].y
                             : (kk == 2) ? av[i].z : av[i].w;
                    u64 ap = pk2(a, a);
                    #pragma unroll
                    for (int j = 0; j < 4; ++j) ffma2(acc2[i][j], ap, bp[j]);
                }
            }
        }

        float4 c0 = *(const float4*)(Bs[p] + tx * 8);
        float4 c1 = *(const float4*)(Bs[p] + tx * 8 + 4);
        float bias[8] = {c0.x, c0.y, c0.z, c0.w, c1.x, c1.y, c1.z, c1.w};
        #pragma unroll
        for (int i = 0; i < 8; ++i) {
            int node = n0 + ty * 8 + i;
            if (node >= N_NODES) continue;
            float o[8];
            upk2(o[0], o[1], acc2[i][0]); upk2(o[2], o[3], acc2[i][1]);
            upk2(o[4], o[5], acc2[i][2]); upk2(o[6], o[7], acc2[i][3]);
            #pragma unroll
            for (int j = 0; j < 8; ++j) o[j] += bias[j];
            if (p < 3) {
                __half* O = (p == 0) ? g_qh : (p == 1) ? g_kh : g_vh;
                __half2 h2[4];
                #pragma unroll
                for (int j = 0; j < 4; ++j)
                    h2[j] = __floats2half2_rn(o[2 * j], o[2 * j + 1]);
                *(uint4*)(O + node * HC + tx * 8) = *(uint4*)h2;
            } else {
                *(float4*)(g_skip + node * HC + tx * 8) =
                    make_float4(o[0], o[1], o[2], o[3]);
                *(float4*)(g_skip + node * HC + tx * 8 + 4) =
                    make_float4(o[4], o[5], o[6], o[7]);
            }
        }
    }
}

// ----------------------------- fused edge kernel ------------------------------
// Phase 1: e = edge_attr @ We via FFMA2 -> sE (fp32, smem).
// Phase 2: lane l owns cols 4l..4l+3 (head h=l>>3): 8B fp16 gathers of q/k/v,
// alpha reduce over 8 lanes, 8B fp16 vjh store at CSR slot.
__global__ void __launch_bounds__(256, 2)
edge_kernel(const float* __restrict__ edge_attr,
            const void* __restrict__ ei,
            const float* __restrict__ We)
{
    extern __shared__ float sm[];
    float* sA  = sm;                      // 128 * 48   [phase 1]
    float* sWe = sm + 128 * 48;           // 44 * 128   [phase 1]
    float* sE  = sm;                      // 128 * 132  [phase 2]
    const int tid = threadIdx.x;
    const int e0 = blockIdx.x * 128;      // E divisible by 128

    for (int i = tid; i < 128 * ED; i += 256) {
        int r = i / ED, c = i - r * ED;
        sA[r * 48 + c] = edge_attr[(e0 + r) * ED + c];
    }
    for (int i = tid; i < 128; i += 256) {
        sA[i * 48 + 44] = 0.f; sA[i * 48 + 45] = 0.f;
        sA[i * 48 + 46] = 0.f; sA[i * 48 + 47] = 0.f;
    }
    for (int i = tid * 4; i < ED * 128; i += 256 * 4)
        *(float4*)(sWe + i) = *(const float4*)(We + i);
    __syncthreads();

    const int ty = tid >> 4;   // edges ty*8..+7
    const int tx = tid & 15;   // cols  tx*8..+7

    u64 acc2[8][4];
    #pragma unroll
    for (int i = 0; i < 8; ++i)
        #pragma unroll
        for (int j = 0; j < 4; ++j) acc2[i][j] = 0ull;

    for (int k = 0; k < ED; k += 4) {          // 44 = 11 * 4, exact
        float4 av[8];
        #pragma unroll
        for (int i = 0; i < 8; ++i)
            av[i] = *(float4*)(sA + (ty * 8 + i) * 48 + k);
        #pragma unroll
        for (int kk = 0; kk < 4; ++kk) {
            float4 b0 = *(float4*)(sWe + (k + kk) * 128 + tx * 8);
            float4 b1 = *(float4*)(sWe + (k + kk) * 128 + tx * 8 + 4);
            u64 bp[4] = {pk2(b0.x, b0.y), pk2(b0.z, b0.w),
                         pk2(b1.x, b1.y), pk2(b1.z, b1.w)};
            #pragma unroll
            for (int i = 0; i < 8; ++i) {
                float a = (kk == 0) ? av[i].x : (kk == 1) ? av[i].y
                         : (kk == 2) ? av[i].z : av[i].w;
                u64 ap = pk2(a, a);
                #pragma unroll
                for (int j = 0; j < 4; ++j) ffma2(acc2[i][j], ap, bp[j]);
            }
        }
    }
    __syncthreads();   // done reading sA/sWe; sE overwrites them

    #pragma unroll
    for (int i = 0; i < 8; ++i) {
        float a0, a1, a2, a3, a4, a5, a6, a7;
        upk2(a0, a1, acc2[i][0]); upk2(a2, a3, acc2[i][1]);
        upk2(a4, a5, acc2[i][2]); upk2(a6, a7, acc2[i][3]);
        *(float4*)(sE + (ty * 8 + i) * 132 + tx * 8)     = make_float4(a0, a1, a2, a3);
        *(float4*)(sE + (ty * 8 + i) * 132 + tx * 8 + 4) = make_float4(a4, a5, a6, a7);
    }
    __syncthreads();

    const int w = tid >> 5, l = tid & 31;
    const int h = l >> 3;                 // head owned by this lane
    const int c0 = 4 * l;                 // first of 4 cols owned
    for (int it = 0; it < 16; ++it) {
        int eloc = w * 16 + it;
        int e = e0 + eloc;
        int src = ld_src(ei, e);
        int dst = ld_dst(ei, e);
        src = min(max(src, 0), N_NODES - 1);
        dst = min(max(dst, 0), N_NODES - 1);
        int pos = g_pos[e];

        float4 ev = *(float4*)(sE + eloc * 132 + c0);
        uint2 qr = *(const uint2*)(g_qh + dst * HC + c0);
        uint2 kr = *(const uint2*)(g_kh + src * HC + c0);
        uint2 vr = *(const uint2*)(g_vh + src * HC + c0);
        float2 q01 = __half22float2(*(__half2*)&qr.x);
        float2 q23 = __half22float2(*(__half2*)&qr.y);
        float2 k01 = __half22float2(*(__half2*)&kr.x);
        float2 k23 = __half22float2(*(__half2*)&kr.y);
        float2 v01 = __half22float2(*(__half2*)&vr.x);
        float2 v23 = __half22float2(*(__half2*)&vr.y);

        float kj0 = k01.x + ev.x, kj1 = k01.y + ev.y;
        float kj2 = k23.x + ev.z, kj3 = k23.y + ev.w;
        float part = q01.x * kj0 + q01.y * kj1 + q23.x * kj2 + q23.y * kj3;

        __half2 vj01 = __floats2half2_rn(v01.x + ev.x, v01.y + ev.y);
        __half2 vj23 = __floats2half2_rn(v23.x + ev.z, v23.y + ev.w);
        uint2 vjw; *(__half2*)&vjw.x = vj01; *(__half2*)&vjw.y = vj23;
        *(uint2*)(g_vjh + pos * HC + c0) = vjw;

        part += __shfl_xor_sync(0xffffffffu, part, 1);
        part += __shfl_xor_sync(0xffffffffu, part, 2);
        part += __shfl_xor_sync(0xffffffffu, part, 4);
        if ((l & 7) == 0) {
            const float isc = 0.17677669529663689f;   // 1/sqrt(32)
            g_alpha[pos * 4 + h] = part * isc;
        }
    }
}

// ----------------------------- aggregation (online softmax) -------------------
// One warp per node; lane l owns cols 4l..4l+3 (head h=l>>3).
// CSR-ordered alpha/vjh -> fully sequential streaming.
__global__ void agg_kernel(float* __restrict__ out)
{
    int n = (blockIdx.x * blockDim.x + threadIdx.x) >> 5;   // exactly N warps
    int l = threadIdx.x & 31;
    const int h = l >> 3;
    const int c0 = 4 * l;
    int beg = g_off[n], end = g_off[n + 1];
    float m = -1e30f, den = 0.f;
    float acc0 = 0.f, acc1 = 0.f, acc2 = 0.f, acc3 = 0.f;
    for (int i = beg; i < end; ++i) {
        float a = g_alpha[i * 4 + h];
        uint2 vr = *(const uint2*)(g_vjh + i * HC + c0);
        float2 v01 = __half22float2(*(__half2*)&vr.x);
        float2 v23 = __half22float2(*(__half2*)&vr.y);
        float nm = fmaxf(m, a);
        float sc = __expf(m - nm);
        float wt = __expf(a - nm);
        den = den * sc + wt;
        acc0 = acc0 * sc + wt * v01.x;
        acc1 = acc1 * sc + wt * v01.y;
        acc2 = acc2 * sc + wt * v23.x;
        acc3 = acc3 * sc + wt * v23.y;
        m = nm;
    }
    float inv = 1.f / (den + 1e-16f);
    float4 sk = *(const float4*)(g_skip + n * HC + c0);
    *(float4*)(out + n * HC + c0) =
        make_float4(acc0 * inv + sk.x, acc1 * inv + sk.y,
                    acc2 * inv + sk.z, acc3 * inv + sk.w);
}

// ----------------------------- launch -----------------------------------------
extern "C" void kernel_launch(void* const* d_in, const int* in_sizes, int n_in,
                              void* d_out, int out_size)
{
    const float* x   = (const float*)d_in[0];
    const void*  ei  = d_in[1];
    const float* ea  = (const float*)d_in[2];
    const float* Wq  = (const float*)d_in[3];
    const float* bq  = (const float*)d_in[4];
    const float* Wk  = (const float*)d_in[5];
    const float* bk  = (const float*)d_in[6];
    const float* Wv  = (const float*)d_in[7];
    const float* bv  = (const float*)d_in[8];
    const float* We  = (const float*)d_in[9];
    const float* Wsk = (const float*)d_in[10];
    const float* bsk = (const float*)d_in[11];
    float* out = (float*)d_out;

    const int smem_node = (128 * 132 + 128 * 128) * 4;   // 130 KB
    const int smem_edge = (128 * 132) * 4;               // 67.6 KB
    cudaFuncSetAttribute(node_proj_kernel,
                         cudaFuncAttributeMaxDynamicSharedMemorySize, smem_node);
    cudaFuncSetAttribute(edge_kernel,
                         cudaFuncAttributeMaxDynamicSharedMemorySize, smem_edge);

    detect_kernel<<<1, 256>>>((const int*)ei);
    zero_counts_kernel<<<(N_NODES + 255) / 256, 256>>>();
    count_kernel<<<E_EDGES / 256, 256>>>(ei);
    scan1_kernel<<<SCAN_B, 256>>>();
    scan2_kernel<<<1, 256>>>();
    scan3_kernel<<<SCAN_B, 256>>>();
    fill_kernel<<<E_EDGES / 256, 256>>>(ei);

    node_proj_kernel<<<(N_NODES + 127) / 128, 256, smem_node>>>(
        x, Wq, bq, Wk, bk, Wv, bv, Wsk, bsk);
    edge_kernel<<<E_EDGES / 128, 256, smem_edge>>>(ea, ei, We);
    agg_kernel<<<(N_NODES * 32) / 256, 256>>>(out);
}

// round 6
// speedup vs baseline: 3.8772x; 1.4312x over previous
#include <cuda_runtime.h>
#include <cuda_fp16.h>

#define N_NODES 50000
#define E_EDGES 800000
#define NIN     128
#define HC      128
#define ED      44
#define NHEAD   4
#define SCAN_B  196   // ceil(N_NODES/256)

// ----------------------------- scratch (static device globals) ---------------
__device__ __half g_qh  [N_NODES * HC];
__device__ __half g_kh  [N_NODES * HC];
__device__ __half g_vh  [N_NODES * HC];
__device__ __half g_skip[N_NODES * HC];
__device__ __half g_vjh [E_EDGES * HC];      // v[src]+e, fp16, CSR-ordered
__device__ float  g_alpha[E_EDGES * NHEAD];  // logits, CSR-ordered
__device__ int    g_count[N_NODES];
__device__ int    g_cur  [N_NODES];
__device__ int    g_off  [N_NODES + 1];
__device__ int    g_pos  [E_EDGES];          // CSR slot of each edge
__device__ int    g_bsum [SCAN_B];
__device__ int    g_boff [SCAN_B];
__device__ int    g_is64;

// ----------------------------- mma helpers -----------------------------------
__device__ __forceinline__ unsigned smem_u32(const void* p)
{
    return (unsigned)__cvta_generic_to_shared(p);
}
__device__ __forceinline__ void ldsm_x4(unsigned addr, unsigned& r0, unsigned& r1,
                                        unsigned& r2, unsigned& r3)
{
    asm volatile("ldmatrix.sync.aligned.m8n8.x4.shared.b16 {%0,%1,%2,%3}, [%4];"
                 : "=r"(r0), "=r"(r1), "=r"(r2), "=r"(r3) : "r"(addr));
}
__device__ __forceinline__ void ldsm_x4_t(unsigned addr, unsigned& r0, unsigned& r1,
                                          unsigned& r2, unsigned& r3)
{
    asm volatile("ldmatrix.sync.aligned.m8n8.x4.trans.shared.b16 {%0,%1,%2,%3}, [%4];"
                 : "=r"(r0), "=r"(r1), "=r"(r2), "=r"(r3) : "r"(addr));
}
__device__ __forceinline__ void mma16816(float* c, unsigned a0, unsigned a1,
                                         unsigned a2, unsigned a3,
                                         unsigned b0, unsigned b1)
{
    asm volatile(
        "mma.sync.aligned.m16n8k16.row.col.f32.f16.f16.f32 "
        "{%0,%1,%2,%3}, {%4,%5,%6,%7}, {%8,%9}, {%0,%1,%2,%3};"
        : "+f"(c[0]), "+f"(c[1]), "+f"(c[2]), "+f"(c[3])
        : "r"(a0), "r"(a1), "r"(a2), "r"(a3), "r"(b0), "r"(b1));
}

// ----------------------------- dtype detection -------------------------------
__global__ void detect_kernel(const int* __restrict__ w)
{
    __shared__ int s[256];
    int t = threadIdx.x;
    int acc = 0;
    for (int i = t; i < 8192; i += 256) acc |= w[2 * i + 1];
    s[t] = acc;
    __syncthreads();
    for (int step = 128; step > 0; step >>= 1) {
        if (t < step) s[t] |= s[t + step];
        __syncthreads();
    }
    if (t == 0) g_is64 = (s[0] == 0) ? 1 : 0;
}

__device__ __forceinline__ int ld_src(const void* ei, int e)
{
    return g_is64 ? (int)((const long long*)ei)[e] : ((const int*)ei)[e];
}
__device__ __forceinline__ int ld_dst(const void* ei, int e)
{
    return g_is64 ? (int)((const long long*)ei)[E_EDGES + e]
                  : ((const int*)ei)[E_EDGES + e];
}

// ----------------------------- CSR build -------------------------------------
__global__ void zero_counts_kernel()
{
    int i = blockIdx.x * blockDim.x + threadIdx.x;
    if (i < N_NODES) g_count[i] = 0;
}

__global__ void count_kernel(const void* __restrict__ ei)
{
    int e = blockIdx.x * blockDim.x + threadIdx.x;
    int dst = ld_dst(ei, e);
    if (dst >= 0 && dst < N_NODES) atomicAdd(&g_count[dst], 1);
}

__device__ __forceinline__ int block_incl_scan(int v, int* ws)
{
    const int lane = threadIdx.x & 31, wid = threadIdx.x >> 5;
    int incl = v;
    #pragma unroll
    for (int s = 1; s < 32; s <<= 1) {
        int o = __shfl_up_sync(0xffffffffu, incl, s);
        if (lane >= s) incl += o;
    }
    if (lane == 31) ws[wid] = incl;
    __syncthreads();
    if (wid == 0) {
        int wv = (lane < 8) ? ws[lane] : 0;
        int wi = wv;
        #pragma unroll
        for (int s = 1; s < 8; s <<= 1) {
            int o = __shfl_up_sync(0xffffffffu, wi, s);
            if (lane >= s) wi += o;
        }
        if (lane < 8) ws[lane] = wi - wv;
    }
    __syncthreads();
    return ws[wid] + incl;
}

__global__ void scan1_kernel()
{
    __shared__ int ws[8];
    int idx = blockIdx.x * 256 + threadIdx.x;
    int v = (idx < N_NODES) ? g_count[idx] : 0;
    int incl = block_incl_scan(v, ws);
    if (threadIdx.x == 255) g_bsum[blockIdx.x] = incl;
}

__global__ void scan2_kernel()
{
    __shared__ int ws[8];
    int t = threadIdx.x;
    int v = (t < SCAN_B) ? g_bsum[t] : 0;
    int incl = block_incl_scan(v, ws);
    if (t < SCAN_B) g_boff[t] = incl - v;
    if (t == SCAN_B - 1) g_off[N_NODES] = incl;
}

__global__ void scan3_kernel()
{
    __shared__ int ws[8];
    int idx = blockIdx.x * 256 + threadIdx.x;
    int v = (idx < N_NODES) ? g_count[idx] : 0;
    int incl = block_incl_scan(v, ws);
    if (idx < N_NODES) {
        int off = g_boff[blockIdx.x] + incl - v;
        g_off[idx] = off;
        g_cur[idx] = off;
    }
}

__global__ void fill_kernel(const void* __restrict__ ei)
{
    int e = blockIdx.x * blockDim.x + threadIdx.x;
    int dst = ld_dst(ei, e);
    int pos = 0;
    if (dst >= 0 && dst < N_NODES) pos = atomicAdd(&g_cur[dst], 1);
    g_pos[e] = pos;
}

// ----------------------------- node projections (HMMA) ------------------------
// 128 nodes x 128 cols per block, 8 warps, warp = 16 rows x 128 cols.
// sX/sW fp16, stride 136 halves (row stagger 4 banks -> conflict-free ldmatrix).
// Output staged through sW region (aliased) after a sync, then 16B stores.
#define NSTR 136
__global__ void __launch_bounds__(256, 2)
node_proj_kernel(const float* __restrict__ x,
                 const float* __restrict__ Wq, const float* __restrict__ bq,
                 const float* __restrict__ Wk, const float* __restrict__ bk,
                 const float* __restrict__ Wv, const float* __restrict__ bv,
                 const float* __restrict__ Wsk, const float* __restrict__ bsk)
{
    extern __shared__ __half smh[];
    __half* sX = smh;                 // 128 x NSTR
    __half* sW = smh + 128 * NSTR;    // 128 x NSTR  (aliased as output staging)
    const int tid = threadIdx.x;
    const int warp = tid >> 5, lane = tid & 31;
    const int n0 = blockIdx.x * 128;

    for (int i = tid * 4; i < 128 * 128; i += 256 * 4) {
        int r = i >> 7, c = i & 127;
        int node = n0 + r;
        float4 val = make_float4(0.f, 0.f, 0.f, 0.f);
        if (node < N_NODES) val = *(const float4*)(x + node * NIN + c);
        __half2 h0 = __floats2half2_rn(val.x, val.y);
        __half2 h1 = __floats2half2_rn(val.z, val.w);
        uint2 pk; *(__half2*)&pk.x = h0; *(__half2*)&pk.y = h1;
        *(uint2*)(sX + r * NSTR + c) = pk;
    }

    const float* Ws[4] = {Wq, Wk, Wv, Wsk};
    const float* Bs[4] = {bq, bk, bv, bsk};
    __half* Os[4] = {g_qh, g_kh, g_vh, g_skip};

    const int row0 = warp * 16;
    const int dr = lane >> 2;              // 0..7
    const int dc = 2 * (lane & 3);         // 0,2,4,6

    for (int p = 0; p < 4; ++p) {
        __syncthreads();                   // sW free (prev staging consumed)
        const float* W = Ws[p];
        for (int i = tid * 4; i < 128 * 128; i += 256 * 4) {
            int r = i >> 7, c = i & 127;
            float4 val = *(const float4*)(W + i);
            __half2 h0 = __floats2half2_rn(val.x, val.y);
            __half2 h1 = __floats2half2_rn(val.z, val.w);
            uint2 pk; *(__half2*)&pk.x = h0; *(__half2*)&pk.y = h1;
            *(uint2*)(sW + r * NSTR + c) = pk;
        }
        __syncthreads();

        float acc[16][4];
        #pragma unroll
        for (int t = 0; t < 16; ++t)
            #pragma unroll
            for (int j = 0; j < 4; ++j) acc[t][j] = 0.f;

        #pragma unroll
        for (int kc = 0; kc < 8; ++kc) {
            int k0 = kc * 16;
            unsigned a0, a1, a2, a3;
            {
                int r = row0 + (lane & 15);
                int c = k0 + 8 * (lane >> 4);
                ldsm_x4(smem_u32(sX + r * NSTR + c), a0, a1, a2, a3);
            }
            #pragma unroll
            for (int nt = 0; nt < 8; ++nt) {
                int nn = nt * 16;
                unsigned b0, b1, b2, b3;
                int r = k0 + (lane & 15);
                int c = nn + 8 * (lane >> 4);
                ldsm_x4_t(smem_u32(sW + r * NSTR + c), b0, b1, b2, b3);
                mma16816(acc[2 * nt],     a0, a1, a2, a3, b0, b1);
                mma16816(acc[2 * nt + 1], a0, a1, a2, a3, b2, b3);
            }
        }
        __syncthreads();                   // done reading sW -> reuse as staging

        const float* bias = Bs[p];
        #pragma unroll
        for (int t = 0; t < 16; ++t) {
            int c = t * 8 + dc;
            float b0v = bias[c], b1v = bias[c + 1];
            __half2 lo = __floats2half2_rn(acc[t][0] + b0v, acc[t][1] + b1v);
            __half2 hi = __floats2half2_rn(acc[t][2] + b0v, acc[t][3] + b1v);
            *(__half2*)(sW + (row0 + dr) * NSTR + c)     = lo;
            *(__half2*)(sW + (row0 + dr + 8) * NSTR + c) = hi;
        }
        __syncwarp();

        __half* O = Os[p];
        for (int i = lane; i < 16 * 16; i += 32) {     // 16 rows x 16 uint4
            int r = i >> 4, ch = i & 15;
            int node = n0 + row0 + r;
            if (node < N_NODES)
                *(uint4*)(O + node * HC + ch * 8) =
                    *(uint4*)(sW + (row0 + r) * NSTR + ch * 8);
        }
    }
}

// ----------------------------- fused edge kernel (HMMA) -----------------------
// Phase 1: e = edge_attr @ We via m16n8k16, K padded to 48.
// Each warp computes edges 16w..16w+15 (all 128 cols) and stores to sE (fp16).
// Phase 2 (same warp, __syncwarp only): gathers + alpha + vjh.
#define ASTR 72
#define WSTR 136
__global__ void __launch_bounds__(256, 2)
edge_kernel(const float* __restrict__ edge_attr,
            const void* __restrict__ ei,
            const float* __restrict__ We)
{
    extern __shared__ __half smh[];
    __half* sA  = smh;                         // 128 x ASTR  (K in cols 0..47)
    __half* sWe = smh + 128 * ASTR;            // 48 x WSTR
    __half* sE  = sWe + 48 * WSTR;             // 128 x WSTR
    const int tid = threadIdx.x;
    const int warp = tid >> 5, lane = tid & 31;
    const int e0 = blockIdx.x * 128;           // E divisible by 128

    for (int i = tid; i < 128 * ED; i += 256) {
        int r = i / ED, c = i - r * ED;
        sA[r * ASTR + c] = __float2half(edge_attr[(e0 + r) * ED + c]);
    }
    for (int i = tid; i < 128 * 4; i += 256) { // zero K pad cols 44..47
        int r = i >> 2, c = 44 + (i & 3);
        sA[r * ASTR + c] = __float2half(0.f);
    }
    for (int i = tid; i < ED * 128; i += 256) {
        int r = i >> 7, c = i & 127;
        sWe[r * WSTR + c] = __float2half(We[i]);
    }
    for (int i = tid; i < 4 * 128; i += 256) { // zero K pad rows 44..47
        int r = 44 + (i >> 7), c = i & 127;
        sWe[r * WSTR + c] = __float2half(0.f);
    }
    __syncthreads();

    const int row0 = warp * 16;
    const int dr = lane >> 2;
    const int dc = 2 * (lane & 3);

    float acc[16][4];
    #pragma unroll
    for (int t = 0; t < 16; ++t)
        #pragma unroll
        for (int j = 0; j < 4; ++j) acc[t][j] = 0.f;

    #pragma unroll
    for (int kc = 0; kc < 3; ++kc) {
        int k0 = kc * 16;
        unsigned a0, a1, a2, a3;
        {
            int r = row0 + (lane & 15);
            int c = k0 + 8 * (lane >> 4);
            ldsm_x4(smem_u32(sA + r * ASTR + c), a0, a1, a2, a3);
        }
        #pragma unroll
        for (int nt = 0; nt < 8; ++nt) {
            int nn = nt * 16;
            unsigned b0, b1, b2, b3;
            int r = k0 + (lane & 15);
            int c = nn + 8 * (lane >> 4);
            ldsm_x4_t(smem_u32(sWe + r * WSTR + c), b0, b1, b2, b3);
            mma16816(acc[2 * nt],     a0, a1, a2, a3, b0, b1);
            mma16816(acc[2 * nt + 1], a0, a1, a2, a3, b2, b3);
        }
    }

    // stage e tile (fp16) -- own rows only, warp-local sync suffices
    #pragma unroll
    for (int t = 0; t < 16; ++t) {
        int c = t * 8 + dc;
        *(__half2*)(sE + (row0 + dr) * WSTR + c) =
            __floats2half2_rn(acc[t][0], acc[t][1]);
        *(__half2*)(sE + (row0 + dr + 8) * WSTR + c) =
            __floats2half2_rn(acc[t][2], acc[t][3]);
    }
    __syncwarp();

    const int h = lane >> 3;               // head owned by this lane
    const int c0 = 4 * lane;               // first of 4 cols owned
    for (int it = 0; it < 16; ++it) {
        int eloc = row0 + it;
        int e = e0 + eloc;
        int src = ld_src(ei, e);
        int dst = ld_dst(ei, e);
        src = min(max(src, 0), N_NODES - 1);
        dst = min(max(dst, 0), N_NODES - 1);
        int pos = g_pos[e];

        uint2 er = *(uint2*)(sE + eloc * WSTR + c0);
        float2 e01 = __half22float2(*(__half2*)&er.x);
        float2 e23 = __half22float2(*(__half2*)&er.y);
        uint2 qr = *(const uint2*)(g_qh + dst * HC + c0);
        uint2 kr = *(const uint2*)(g_kh + src * HC + c0);
        uint2 vr = *(const uint2*)(g_vh + src * HC + c0);
        float2 q01 = __half22float2(*(__half2*)&qr.x);
        float2 q23 = __half22float2(*(__half2*)&qr.y);
        float2 k01 = __half22float2(*(__half2*)&kr.x);
        float2 k23 = __half22float2(*(__half2*)&kr.y);
        float2 v01 = __half22float2(*(__half2*)&vr.x);
        float2 v23 = __half22float2(*(__half2*)&vr.y);

        float part = q01.x * (k01.x + e01.x) + q01.y * (k01.y + e01.y)
                   + q23.x * (k23.x + e23.x) + q23.y * (k23.y + e23.y);

        __half2 vj01 = __floats2half2_rn(v01.x + e01.x, v01.y + e01.y);
        __half2 vj23 = __floats2half2_rn(v23.x + e23.x, v23.y + e23.y);
        uint2 vjw; *(__half2*)&vjw.x = vj01; *(__half2*)&vjw.y = vj23;
        *(uint2*)(g_vjh + pos * HC + c0) = vjw;

        part += __shfl_xor_sync(0xffffffffu, part, 1);
        part += __shfl_xor_sync(0xffffffffu, part, 2);
        part += __shfl_xor_sync(0xffffffffu, part, 4);
        if ((lane & 7) == 0) {
            const float isc = 0.17677669529663689f;   // 1/sqrt(32)
            g_alpha[pos * 4 + h] = part * isc;
        }
    }
}

// ----------------------------- aggregation (online softmax) -------------------
__global__ void agg_kernel(float* __restrict__ out)
{
    int n = (blockIdx.x * blockDim.x + threadIdx.x) >> 5;   // exactly N warps
    int l = threadIdx.x & 31;
    const int h = l >> 3;
    const int c0 = 4 * l;
    int beg = g_off[n], end = g_off[n + 1];
    float m = -1e30f, den = 0.f;
    float acc0 = 0.f, acc1 = 0.f, acc2 = 0.f, acc3 = 0.f;
    for (int i = beg; i < end; ++i) {
        float a = g_alpha[i * 4 + h];
        uint2 vr = *(const uint2*)(g_vjh + i * HC + c0);
        float2 v01 = __half22float2(*(__half2*)&vr.x);
        float2 v23 = __half22float2(*(__half2*)&vr.y);
        float nm = fmaxf(m, a);
        float sc = __expf(m - nm);
        float wt = __expf(a - nm);
        den = den * sc + wt;
        acc0 = acc0 * sc + wt * v01.x;
        acc1 = acc1 * sc + wt * v01.y;
        acc2 = acc2 * sc + wt * v23.x;
        acc3 = acc3 * sc + wt * v23.y;
        m = nm;
    }
    float inv = 1.f / (den + 1e-16f);
    uint2 skr = *(const uint2*)(g_skip + n * HC + c0);
    float2 s01 = __half22float2(*(__half2*)&skr.x);
    float2 s23 = __half22float2(*(__half2*)&skr.y);
    *(float4*)(out + n * HC + c0) =
        make_float4(acc0 * inv + s01.x, acc1 * inv + s01.y,
                    acc2 * inv + s23.x, acc3 * inv + s23.y);
}

// ----------------------------- launch -----------------------------------------
extern "C" void kernel_launch(void* const* d_in, const int* in_sizes, int n_in,
                              void* d_out, int out_size)
{
    const float* x   = (const float*)d_in[0];
    const void*  ei  = d_in[1];
    const float* ea  = (const float*)d_in[2];
    const float* Wq  = (const float*)d_in[3];
    const float* bq  = (const float*)d_in[4];
    const float* Wk  = (const float*)d_in[5];
    const float* bk  = (const float*)d_in[6];
    const float* Wv  = (const float*)d_in[7];
    const float* bv  = (const float*)d_in[8];
    const float* We  = (const float*)d_in[9];
    const float* Wsk = (const float*)d_in[10];
    const float* bsk = (const float*)d_in[11];
    float* out = (float*)d_out;

    const int smem_node = 2 * 128 * NSTR * 2;                       // 69.6 KB
    const int smem_edge = (128 * ASTR + 48 * WSTR + 128 * WSTR) * 2; // 66.3 KB
    cudaFuncSetAttribute(node_proj_kernel,
                         cudaFuncAttributeMaxDynamicSharedMemorySize, smem_node);
    cudaFuncSetAttribute(edge_kernel,
                         cudaFuncAttributeMaxDynamicSharedMemorySize, smem_edge);

    detect_kernel<<<1, 256>>>((const int*)ei);
    zero_counts_kernel<<<(N_NODES + 255) / 256, 256>>>();
    count_kernel<<<E_EDGES / 256, 256>>>(ei);
    scan1_kernel<<<SCAN_B, 256>>>();
    scan2_kernel<<<1, 256>>>();
    scan3_kernel<<<SCAN_B, 256>>>();
    fill_kernel<<<E_EDGES / 256, 256>>>(ei);

    node_proj_kernel<<<(N_NODES + 127) / 128, 256, smem_node>>>(
        x, Wq, bq, Wk, bk, Wv, bv, Wsk, bsk);
    edge_kernel<<<E_EDGES / 128, 256, smem_edge>>>(ea, ei, We);
    agg_kernel<<<(N_NODES * 32) / 256, 256>>>(out);
}

// round 7
// speedup vs baseline: 4.5003x; 1.1607x over previous
#include <cuda_runtime.h>
#include <cuda_fp16.h>

#define N_NODES 50000
#define E_EDGES 800000
#define NIN     128
#define HC      128
#define ED      44
#define NHEAD   4
#define SCAN_B  196   // ceil(N_NODES/256)

// ----------------------------- scratch (static device globals) ---------------
__device__ __half g_qh  [N_NODES * HC];
__device__ __half g_kh  [N_NODES * HC];
__device__ __half g_vh  [N_NODES * HC];
__device__ __half g_skip[N_NODES * HC];
__device__ __half g_vjh [E_EDGES * HC];      // v[src]+e, fp16, CSR-ordered
__device__ float  g_alpha[E_EDGES * NHEAD];  // logits, CSR-ordered
__device__ int    g_count[N_NODES];
__device__ int    g_cur  [N_NODES];
__device__ int    g_off  [N_NODES + 1];
__device__ int    g_pos  [E_EDGES];          // CSR slot of each edge
__device__ int    g_bsum [SCAN_B];
__device__ int    g_boff [SCAN_B];
__device__ int    g_is64;

// ----------------------------- mma helpers -----------------------------------
__device__ __forceinline__ unsigned smem_u32(const void* p)
{
    return (unsigned)__cvta_generic_to_shared(p);
}
__device__ __forceinline__ void ldsm_x4(unsigned addr, unsigned& r0, unsigned& r1,
                                        unsigned& r2, unsigned& r3)
{
    asm volatile("ldmatrix.sync.aligned.m8n8.x4.shared.b16 {%0,%1,%2,%3}, [%4];"
                 : "=r"(r0), "=r"(r1), "=r"(r2), "=r"(r3) : "r"(addr));
}
__device__ __forceinline__ void ldsm_x4_t(unsigned addr, unsigned& r0, unsigned& r1,
                                          unsigned& r2, unsigned& r3)
{
    asm volatile("ldmatrix.sync.aligned.m8n8.x4.trans.shared.b16 {%0,%1,%2,%3}, [%4];"
                 : "=r"(r0), "=r"(r1), "=r"(r2), "=r"(r3) : "r"(addr));
}
__device__ __forceinline__ void mma16816(float* c, unsigned a0, unsigned a1,
                                         unsigned a2, unsigned a3,
                                         unsigned b0, unsigned b1)
{
    asm volatile(
        "mma.sync.aligned.m16n8k16.row.col.f32.f16.f16.f32 "
        "{%0,%1,%2,%3}, {%4,%5,%6,%7}, {%8,%9}, {%0,%1,%2,%3};"
        : "+f"(c[0]), "+f"(c[1]), "+f"(c[2]), "+f"(c[3])
        : "r"(a0), "r"(a1), "r"(a2), "r"(a3), "r"(b0), "r"(b1));
}

// ----------------------------- dtype detection -------------------------------
__global__ void detect_kernel(const int* __restrict__ w)
{
    __shared__ int s[256];
    int t = threadIdx.x;
    int acc = 0;
    for (int i = t; i < 8192; i += 256) acc |= w[2 * i + 1];
    s[t] = acc;
    __syncthreads();
    for (int step = 128; step > 0; step >>= 1) {
        if (t < step) s[t] |= s[t + step];
        __syncthreads();
    }
    if (t == 0) g_is64 = (s[0] == 0) ? 1 : 0;
}

__device__ __forceinline__ int ld_src(const void* ei, int e)
{
    return g_is64 ? (int)((const long long*)ei)[e] : ((const int*)ei)[e];
}
__device__ __forceinline__ int ld_dst(const void* ei, int e)
{
    return g_is64 ? (int)((const long long*)ei)[E_EDGES + e]
                  : ((const int*)ei)[E_EDGES + e];
}

// ----------------------------- CSR build -------------------------------------
__global__ void zero_counts_kernel()
{
    int i = blockIdx.x * blockDim.x + threadIdx.x;
    if (i < N_NODES) g_count[i] = 0;
}

__global__ void count_kernel(const void* __restrict__ ei)
{
    int e = blockIdx.x * blockDim.x + threadIdx.x;
    int dst = ld_dst(ei, e);
    if (dst >= 0 && dst < N_NODES) atomicAdd(&g_count[dst], 1);
}

__device__ __forceinline__ int block_incl_scan(int v, int* ws)
{
    const int lane = threadIdx.x & 31, wid = threadIdx.x >> 5;
    int incl = v;
    #pragma unroll
    for (int s = 1; s < 32; s <<= 1) {
        int o = __shfl_up_sync(0xffffffffu, incl, s);
        if (lane >= s) incl += o;
    }
    if (lane == 31) ws[wid] = incl;
    __syncthreads();
    if (wid == 0) {
        int wv = (lane < 8) ? ws[lane] : 0;
        int wi = wv;
        #pragma unroll
        for (int s = 1; s < 8; s <<= 1) {
            int o = __shfl_up_sync(0xffffffffu, wi, s);
            if (lane >= s) wi += o;
        }
        if (lane < 8) ws[lane] = wi - wv;
    }
    __syncthreads();
    return ws[wid] + incl;
}

__global__ void scan1_kernel()
{
    __shared__ int ws[8];
    int idx = blockIdx.x * 256 + threadIdx.x;
    int v = (idx < N_NODES) ? g_count[idx] : 0;
    int incl = block_incl_scan(v, ws);
    if (threadIdx.x == 255) g_bsum[blockIdx.x] = incl;
}

__global__ void scan2_kernel()
{
    __shared__ int ws[8];
    int t = threadIdx.x;
    int v = (t < SCAN_B) ? g_bsum[t] : 0;
    int incl = block_incl_scan(v, ws);
    if (t < SCAN_B) g_boff[t] = incl - v;
    if (t == SCAN_B - 1) g_off[N_NODES] = incl;
}

__global__ void scan3_kernel()
{
    __shared__ int ws[8];
    int idx = blockIdx.x * 256 + threadIdx.x;
    int v = (idx < N_NODES) ? g_count[idx] : 0;
    int incl = block_incl_scan(v, ws);
    if (idx < N_NODES) {
        int off = g_boff[blockIdx.x] + incl - v;
        g_off[idx] = off;
        g_cur[idx] = off;
    }
}

__global__ void fill_kernel(const void* __restrict__ ei)
{
    int e = blockIdx.x * blockDim.x + threadIdx.x;
    int dst = ld_dst(ei, e);
    int pos = 0;
    if (dst >= 0 && dst < N_NODES) pos = atomicAdd(&g_cur[dst], 1);
    g_pos[e] = pos;
}

// ----------------------------- node projections (HMMA) ------------------------
#define NSTR 136
__global__ void __launch_bounds__(256, 2)
node_proj_kernel(const float* __restrict__ x,
                 const float* __restrict__ Wq, const float* __restrict__ bq,
                 const float* __restrict__ Wk, const float* __restrict__ bk,
                 const float* __restrict__ Wv, const float* __restrict__ bv,
                 const float* __restrict__ Wsk, const float* __restrict__ bsk)
{
    extern __shared__ __half smh[];
    __half* sX = smh;                 // 128 x NSTR
    __half* sW = smh + 128 * NSTR;    // 128 x NSTR  (aliased as output staging)
    const int tid = threadIdx.x;
    const int warp = tid >> 5, lane = tid & 31;
    const int n0 = blockIdx.x * 128;

    for (int i = tid * 4; i < 128 * 128; i += 256 * 4) {
        int r = i >> 7, c = i & 127;
        int node = n0 + r;
        float4 val = make_float4(0.f, 0.f, 0.f, 0.f);
        if (node < N_NODES) val = *(const float4*)(x + node * NIN + c);
        __half2 h0 = __floats2half2_rn(val.x, val.y);
        __half2 h1 = __floats2half2_rn(val.z, val.w);
        uint2 pk; *(__half2*)&pk.x = h0; *(__half2*)&pk.y = h1;
        *(uint2*)(sX + r * NSTR + c) = pk;
    }

    const float* Ws[4] = {Wq, Wk, Wv, Wsk};
    const float* Bs[4] = {bq, bk, bv, bsk};
    __half* Os[4] = {g_qh, g_kh, g_vh, g_skip};

    const int row0 = warp * 16;
    const int dr = lane >> 2;              // 0..7
    const int dc = 2 * (lane & 3);         // 0,2,4,6

    for (int p = 0; p < 4; ++p) {
        __syncthreads();                   // sW free (prev staging consumed)
        const float* W = Ws[p];
        for (int i = tid * 4; i < 128 * 128; i += 256 * 4) {
            int r = i >> 7, c = i & 127;
            float4 val = *(const float4*)(W + i);
            __half2 h0 = __floats2half2_rn(val.x, val.y);
            __half2 h1 = __floats2half2_rn(val.z, val.w);
            uint2 pk; *(__half2*)&pk.x = h0; *(__half2*)&pk.y = h1;
            *(uint2*)(sW + r * NSTR + c) = pk;
        }
        __syncthreads();

        float acc[16][4];
        #pragma unroll
        for (int t = 0; t < 16; ++t)
            #pragma unroll
            for (int j = 0; j < 4; ++j) acc[t][j] = 0.f;

        #pragma unroll
        for (int kc = 0; kc < 8; ++kc) {
            int k0 = kc * 16;
            unsigned a0, a1, a2, a3;
            {
                int r = row0 + (lane & 15);
                int c = k0 + 8 * (lane >> 4);
                ldsm_x4(smem_u32(sX + r * NSTR + c), a0, a1, a2, a3);
            }
            #pragma unroll
            for (int nt = 0; nt < 8; ++nt) {
                int nn = nt * 16;
                unsigned b0, b1, b2, b3;
                int r = k0 + (lane & 15);
                int c = nn + 8 * (lane >> 4);
                ldsm_x4_t(smem_u32(sW + r * NSTR + c), b0, b1, b2, b3);
                mma16816(acc[2 * nt],     a0, a1, a2, a3, b0, b1);
                mma16816(acc[2 * nt + 1], a0, a1, a2, a3, b2, b3);
            }
        }
        __syncthreads();                   // done reading sW -> reuse as staging

        const float* bias = Bs[p];
        #pragma unroll
        for (int t = 0; t < 16; ++t) {
            int c = t * 8 + dc;
            float b0v = bias[c], b1v = bias[c + 1];
            __half2 lo = __floats2half2_rn(acc[t][0] + b0v, acc[t][1] + b1v);
            __half2 hi = __floats2half2_rn(acc[t][2] + b0v, acc[t][3] + b1v);
            *(__half2*)(sW + (row0 + dr) * NSTR + c)     = lo;
            *(__half2*)(sW + (row0 + dr + 8) * NSTR + c) = hi;
        }
        __syncwarp();

        __half* O = Os[p];
        for (int i = lane; i < 16 * 16; i += 32) {     // 16 rows x 16 uint4
            int r = i >> 4, ch = i & 15;
            int node = n0 + row0 + r;
            if (node < N_NODES)
                *(uint4*)(O + node * HC + ch * 8) =
                    *(uint4*)(sW + (row0 + r) * NSTR + ch * 8);
        }
    }
}

// ----------------------------- fused edge kernel (HMMA) -----------------------
// Phase 1: e = edge_attr @ We via m16n8k16, K padded to 48.
// Phase 2: indices preloaded for all 16 edges; gathers batched 4 edges at a
// time (12 LDG.64 in flight) for high MLP; then dots/reduction/stores.
#define ASTR 72
#define WSTR 136
__global__ void __launch_bounds__(256, 2)
edge_kernel(const float* __restrict__ edge_attr,
            const void* __restrict__ ei,
            const float* __restrict__ We)
{
    extern __shared__ __half smh[];
    __half* sA  = smh;                         // 128 x ASTR  (K in cols 0..47)
    __half* sWe = smh + 128 * ASTR;            // 48 x WSTR
    __half* sE  = sWe + 48 * WSTR;             // 128 x WSTR
    const int tid = threadIdx.x;
    const int warp = tid >> 5, lane = tid & 31;
    const int e0 = blockIdx.x * 128;           // E divisible by 128

    for (int i = tid; i < 128 * ED; i += 256) {
        int r = i / ED, c = i - r * ED;
        sA[r * ASTR + c] = __float2half(edge_attr[(e0 + r) * ED + c]);
    }
    for (int i = tid; i < 128 * 4; i += 256) { // zero K pad cols 44..47
        int r = i >> 2, c = 44 + (i & 3);
        sA[r * ASTR + c] = __float2half(0.f);
    }
    for (int i = tid; i < ED * 128; i += 256) {
        int r = i >> 7, c = i & 127;
        sWe[r * WSTR + c] = __float2half(We[i]);
    }
    for (int i = tid; i < 4 * 128; i += 256) { // zero K pad rows 44..47
        int r = 44 + (i >> 7), c = i & 127;
        sWe[r * WSTR + c] = __float2half(0.f);
    }
    __syncthreads();

    const int row0 = warp * 16;
    const int dr = lane >> 2;
    const int dc = 2 * (lane & 3);

    float acc[16][4];
    #pragma unroll
    for (int t = 0; t < 16; ++t)
        #pragma unroll
        for (int j = 0; j < 4; ++j) acc[t][j] = 0.f;

    #pragma unroll
    for (int kc = 0; kc < 3; ++kc) {
        int k0 = kc * 16;
        unsigned a0, a1, a2, a3;
        {
            int r = row0 + (lane & 15);
            int c = k0 + 8 * (lane >> 4);
            ldsm_x4(smem_u32(sA + r * ASTR + c), a0, a1, a2, a3);
        }
        #pragma unroll
        for (int nt = 0; nt < 8; ++nt) {
            int nn = nt * 16;
            unsigned b0, b1, b2, b3;
            int r = k0 + (lane & 15);
            int c = nn + 8 * (lane >> 4);
            ldsm_x4_t(smem_u32(sWe + r * WSTR + c), b0, b1, b2, b3);
            mma16816(acc[2 * nt],     a0, a1, a2, a3, b0, b1);
            mma16816(acc[2 * nt + 1], a0, a1, a2, a3, b2, b3);
        }
    }

    // stage e tile (fp16) -- own rows only, warp-local sync suffices
    #pragma unroll
    for (int t = 0; t < 16; ++t) {
        int c = t * 8 + dc;
        *(__half2*)(sE + (row0 + dr) * WSTR + c) =
            __floats2half2_rn(acc[t][0], acc[t][1]);
        *(__half2*)(sE + (row0 + dr + 8) * WSTR + c) =
            __floats2half2_rn(acc[t][2], acc[t][3]);
    }
    __syncwarp();

    // preload indices for all 16 edges of this warp (uniform)
    int srcs[16], dsts[16], poss[16];
    #pragma unroll
    for (int it = 0; it < 16; ++it) {
        int e = e0 + row0 + it;
        int s = ld_src(ei, e);
        int d = ld_dst(ei, e);
        srcs[it] = min(max(s, 0), N_NODES - 1);
        dsts[it] = min(max(d, 0), N_NODES - 1);
        poss[it] = g_pos[e];
    }

    const int h = lane >> 3;               // head owned by this lane
    const int c0 = 4 * lane;               // first of 4 cols owned
    const float isc = 0.17677669529663689f; // 1/sqrt(32)

    #pragma unroll
    for (int g = 0; g < 16; g += 4) {
        // issue all 12 gathers before consuming anything
        uint2 qr[4], kr[4], vr[4], er[4];
        #pragma unroll
        for (int j = 0; j < 4; ++j) {
            int it = g + j;
            qr[j] = *(const uint2*)(g_qh + dsts[it] * HC + c0);
            kr[j] = *(const uint2*)(g_kh + srcs[it] * HC + c0);
            vr[j] = *(const uint2*)(g_vh + srcs[it] * HC + c0);
            er[j] = *(uint2*)(sE + (row0 + it) * WSTR + c0);
        }
        float part[4];
        #pragma unroll
        for (int j = 0; j < 4; ++j) {
            float2 e01 = __half22float2(*(__half2*)&er[j].x);
            float2 e23 = __half22float2(*(__half2*)&er[j].y);
            float2 q01 = __half22float2(*(__half2*)&qr[j].x);
            float2 q23 = __half22float2(*(__half2*)&qr[j].y);
            float2 k01 = __half22float2(*(__half2*)&kr[j].x);
            float2 k23 = __half22float2(*(__half2*)&kr[j].y);
            float2 v01 = __half22float2(*(__half2*)&vr[j].x);
            float2 v23 = __half22float2(*(__half2*)&vr[j].y);

            part[j] = q01.x * (k01.x + e01.x) + q01.y * (k01.y + e01.y)
                    + q23.x * (k23.x + e23.x) + q23.y * (k23.y + e23.y);

            __half2 vj01 = __floats2half2_rn(v01.x + e01.x, v01.y + e01.y);
            __half2 vj23 = __floats2half2_rn(v23.x + e23.x, v23.y + e23.y);
            uint2 vjw; *(__half2*)&vjw.x = vj01; *(__half2*)&vjw.y = vj23;
            *(uint2*)(g_vjh + poss[g + j] * HC + c0) = vjw;
        }
        #pragma unroll
        for (int j = 0; j < 4; ++j) {
            part[j] += __shfl_xor_sync(0xffffffffu, part[j], 1);
            part[j] += __shfl_xor_sync(0xffffffffu, part[j], 2);
            part[j] += __shfl_xor_sync(0xffffffffu, part[j], 4);
            if ((lane & 7) == 0)
                g_alpha[poss[g + j] * 4 + h] = part[j] * isc;
        }
    }
}

// ----------------------------- aggregation (two-pass softmax) ------------------
// One warp per node; lane l owns cols 4l..4l+3 (head h=l>>3).
// Pass 1: segment max (4-cyc fmax chain). Pass 2: exp-accumulate (no rescale
// chain, one exp per edge). alpha is L2-hot on the second pass.
__global__ void agg_kernel(float* __restrict__ out)
{
    int n = (blockIdx.x * blockDim.x + threadIdx.x) >> 5;   // exactly N warps
    int l = threadIdx.x & 31;
    const int h = l >> 3;
    const int c0 = 4 * l;
    int beg = g_off[n], end = g_off[n + 1];

    float m = -1e30f;
    for (int i = beg; i < end; ++i)
        m = fmaxf(m, g_alpha[i * 4 + h]);

    float den = 0.f;
    float acc0 = 0.f, acc1 = 0.f, acc2 = 0.f, acc3 = 0.f;
    #pragma unroll 2
    for (int i = beg; i < end; ++i) {
        float a = g_alpha[i * 4 + h];
        uint2 vr = *(const uint2*)(g_vjh + i * HC + c0);
        float2 v01 = __half22float2(*(__half2*)&vr.x);
        float2 v23 = __half22float2(*(__half2*)&vr.y);
        float wt = __expf(a - m);
        den += wt;
        acc0 += wt * v01.x;
        acc1 += wt * v01.y;
        acc2 += wt * v23.x;
        acc3 += wt * v23.y;
    }
    float inv = 1.f / (den + 1e-16f);
    uint2 skr = *(const uint2*)(g_skip + n * HC + c0);
    float2 s01 = __half22float2(*(__half2*)&skr.x);
    float2 s23 = __half22float2(*(__half2*)&skr.y);
    *(float4*)(out + n * HC + c0) =
        make_float4(acc0 * inv + s01.x, acc1 * inv + s01.y,
                    acc2 * inv + s23.x, acc3 * inv + s23.y);
}

// ----------------------------- launch -----------------------------------------
extern "C" void kernel_launch(void* const* d_in, const int* in_sizes, int n_in,
                              void* d_out, int out_size)
{
    const float* x   = (const float*)d_in[0];
    const void*  ei  = d_in[1];
    const float* ea  = (const float*)d_in[2];
    const float* Wq  = (const float*)d_in[3];
    const float* bq  = (const float*)d_in[4];
    const float* Wk  = (const float*)d_in[5];
    const float* bk  = (const float*)d_in[6];
    const float* Wv  = (const float*)d_in[7];
    const float* bv  = (const float*)d_in[8];
    const float* We  = (const float*)d_in[9];
    const float* Wsk = (const float*)d_in[10];
    const float* bsk = (const float*)d_in[11];
    float* out = (float*)d_out;

    const int smem_node = 2 * 128 * NSTR * 2;                       // 69.6 KB
    const int smem_edge = (128 * ASTR + 48 * WSTR + 128 * WSTR) * 2; // 66.3 KB
    cudaFuncSetAttribute(node_proj_kernel,
                         cudaFuncAttributeMaxDynamicSharedMemorySize, smem_node);
    cudaFuncSetAttribute(edge_kernel,
                         cudaFuncAttributeMaxDynamicSharedMemorySize, smem_edge);

    detect_kernel<<<1, 256>>>((const int*)ei);
    zero_counts_kernel<<<(N_NODES + 255) / 256, 256>>>();
    count_kernel<<<E_EDGES / 256, 256>>>(ei);
    scan1_kernel<<<SCAN_B, 256>>>();
    scan2_kernel<<<1, 256>>>();
    scan3_kernel<<<SCAN_B, 256>>>();
    fill_kernel<<<E_EDGES / 256, 256>>>(ei);

    node_proj_kernel<<<(N_NODES + 127) / 128, 256, smem_node>>>(
        x, Wq, bq, Wk, bk, Wv, bv, Wsk, bsk);
    edge_kernel<<<E_EDGES / 128, 256, smem_edge>>>(ea, ei, We);
    agg_kernel<<<(N_NODES * 32) / 256, 256>>>(out);
}

// round 8
// speedup vs baseline: 5.1285x; 1.1396x over previous
#include <cuda_runtime.h>
#include <cuda_fp16.h>

#define N_NODES 50000
#define E_EDGES 800000
#define NIN     128
#define HC      128
#define ED      44
#define NHEAD   4
#define SCAN_B  196   // ceil(N_NODES/256)

// ----------------------------- scratch (static device globals) ---------------
__device__ __half g_qh  [N_NODES * HC];
__device__ __half g_kh  [N_NODES * HC];
__device__ __half g_vh  [N_NODES * HC];
__device__ __half g_skip[N_NODES * HC];
__device__ __half g_e   [E_EDGES * HC];      // e = edge_attr @ We, edge order
__device__ int    g_count[N_NODES];
__device__ int    g_cur  [N_NODES];
__device__ int    g_off  [N_NODES + 1];
__device__ int    g_elist[E_EDGES];          // CSR edge list (by dst)
__device__ int    g_bsum [SCAN_B];
__device__ int    g_boff [SCAN_B];
__device__ int    g_is64;

// ----------------------------- mma helpers -----------------------------------
__device__ __forceinline__ unsigned smem_u32(const void* p)
{
    return (unsigned)__cvta_generic_to_shared(p);
}
__device__ __forceinline__ void ldsm_x4(unsigned addr, unsigned& r0, unsigned& r1,
                                        unsigned& r2, unsigned& r3)
{
    asm volatile("ldmatrix.sync.aligned.m8n8.x4.shared.b16 {%0,%1,%2,%3}, [%4];"
                 : "=r"(r0), "=r"(r1), "=r"(r2), "=r"(r3) : "r"(addr));
}
__device__ __forceinline__ void ldsm_x4_t(unsigned addr, unsigned& r0, unsigned& r1,
                                          unsigned& r2, unsigned& r3)
{
    asm volatile("ldmatrix.sync.aligned.m8n8.x4.trans.shared.b16 {%0,%1,%2,%3}, [%4];"
                 : "=r"(r0), "=r"(r1), "=r"(r2), "=r"(r3) : "r"(addr));
}
__device__ __forceinline__ void mma16816(float* c, unsigned a0, unsigned a1,
                                         unsigned a2, unsigned a3,
                                         unsigned b0, unsigned b1)
{
    asm volatile(
        "mma.sync.aligned.m16n8k16.row.col.f32.f16.f16.f32 "
        "{%0,%1,%2,%3}, {%4,%5,%6,%7}, {%8,%9}, {%0,%1,%2,%3};"
        : "+f"(c[0]), "+f"(c[1]), "+f"(c[2]), "+f"(c[3])
        : "r"(a0), "r"(a1), "r"(a2), "r"(a3), "r"(b0), "r"(b1));
}

// ----------------------------- dtype detection -------------------------------
__global__ void detect_kernel(const int* __restrict__ w)
{
    __shared__ int s[256];
    int t = threadIdx.x;
    int acc = 0;
    for (int i = t; i < 8192; i += 256) acc |= w[2 * i + 1];
    s[t] = acc;
    __syncthreads();
    for (int step = 128; step > 0; step >>= 1) {
        if (t < step) s[t] |= s[t + step];
        __syncthreads();
    }
    if (t == 0) g_is64 = (s[0] == 0) ? 1 : 0;
}

__device__ __forceinline__ int ld_src(const void* ei, int e, int is64)
{
    return is64 ? (int)((const long long*)ei)[e] : ((const int*)ei)[e];
}
__device__ __forceinline__ int ld_dst(const void* ei, int e, int is64)
{
    return is64 ? (int)((const long long*)ei)[E_EDGES + e]
                : ((const int*)ei)[E_EDGES + e];
}

// ----------------------------- CSR build -------------------------------------
__global__ void zero_counts_kernel()
{
    int i = blockIdx.x * blockDim.x + threadIdx.x;
    if (i < N_NODES) g_count[i] = 0;
}

__global__ void count_kernel(const void* __restrict__ ei)
{
    int e = blockIdx.x * blockDim.x + threadIdx.x;
    int dst = ld_dst(ei, e, g_is64);
    if (dst >= 0 && dst < N_NODES) atomicAdd(&g_count[dst], 1);
}

__device__ __forceinline__ int block_incl_scan(int v, int* ws)
{
    const int lane = threadIdx.x & 31, wid = threadIdx.x >> 5;
    int incl = v;
    #pragma unroll
    for (int s = 1; s < 32; s <<= 1) {
        int o = __shfl_up_sync(0xffffffffu, incl, s);
        if (lane >= s) incl += o;
    }
    if (lane == 31) ws[wid] = incl;
    __syncthreads();
    if (wid == 0) {
        int wv = (lane < 8) ? ws[lane] : 0;
        int wi = wv;
        #pragma unroll
        for (int s = 1; s < 8; s <<= 1) {
            int o = __shfl_up_sync(0xffffffffu, wi, s);
            if (lane >= s) wi += o;
        }
        if (lane < 8) ws[lane] = wi - wv;
    }
    __syncthreads();
    return ws[wid] + incl;
}

__global__ void scan1_kernel()
{
    __shared__ int ws[8];
    int idx = blockIdx.x * 256 + threadIdx.x;
    int v = (idx < N_NODES) ? g_count[idx] : 0;
    int incl = block_incl_scan(v, ws);
    if (threadIdx.x == 255) g_bsum[blockIdx.x] = incl;
}

__global__ void scan2_kernel()
{
    __shared__ int ws[8];
    int t = threadIdx.x;
    int v = (t < SCAN_B) ? g_bsum[t] : 0;
    int incl = block_incl_scan(v, ws);
    if (t < SCAN_B) g_boff[t] = incl - v;
    if (t == SCAN_B - 1) g_off[N_NODES] = incl;
}

__global__ void scan3_kernel()
{
    __shared__ int ws[8];
    int idx = blockIdx.x * 256 + threadIdx.x;
    int v = (idx < N_NODES) ? g_count[idx] : 0;
    int incl = block_incl_scan(v, ws);
    if (idx < N_NODES) {
        int off = g_boff[blockIdx.x] + incl - v;
        g_off[idx] = off;
        g_cur[idx] = off;
    }
}

__global__ void fill_kernel(const void* __restrict__ ei)
{
    int e = blockIdx.x * blockDim.x + threadIdx.x;
    int dst = ld_dst(ei, e, g_is64);
    if (dst >= 0 && dst < N_NODES) {
        int pos = atomicAdd(&g_cur[dst], 1);
        g_elist[pos] = e;
    }
}

// ----------------------------- node projections (HMMA) ------------------------
#define NSTR 136
__global__ void __launch_bounds__(256, 2)
node_proj_kernel(const float* __restrict__ x,
                 const float* __restrict__ Wq, const float* __restrict__ bq,
                 const float* __restrict__ Wk, const float* __restrict__ bk,
                 const float* __restrict__ Wv, const float* __restrict__ bv,
                 const float* __restrict__ Wsk, const float* __restrict__ bsk)
{
    extern __shared__ __half smh[];
    __half* sX = smh;                 // 128 x NSTR
    __half* sW = smh + 128 * NSTR;    // 128 x NSTR  (aliased as output staging)
    const int tid = threadIdx.x;
    const int warp = tid >> 5, lane = tid & 31;
    const int n0 = blockIdx.x * 128;

    for (int i = tid * 4; i < 128 * 128; i += 256 * 4) {
        int r = i >> 7, c = i & 127;
        int node = n0 + r;
        float4 val = make_float4(0.f, 0.f, 0.f, 0.f);
        if (node < N_NODES) val = *(const float4*)(x + node * NIN + c);
        __half2 h0 = __floats2half2_rn(val.x, val.y);
        __half2 h1 = __floats2half2_rn(val.z, val.w);
        uint2 pk; *(__half2*)&pk.x = h0; *(__half2*)&pk.y = h1;
        *(uint2*)(sX + r * NSTR + c) = pk;
    }

    const float* Ws[4] = {Wq, Wk, Wv, Wsk};
    const float* Bs[4] = {bq, bk, bv, bsk};
    __half* Os[4] = {g_qh, g_kh, g_vh, g_skip};

    const int row0 = warp * 16;
    const int dr = lane >> 2;              // 0..7
    const int dc = 2 * (lane & 3);         // 0,2,4,6

    for (int p = 0; p < 4; ++p) {
        __syncthreads();                   // sW free (prev staging consumed)
        const float* W = Ws[p];
        for (int i = tid * 4; i < 128 * 128; i += 256 * 4) {
            int r = i >> 7, c = i & 127;
            float4 val = *(const float4*)(W + i);
            __half2 h0 = __floats2half2_rn(val.x, val.y);
            __half2 h1 = __floats2half2_rn(val.z, val.w);
            uint2 pk; *(__half2*)&pk.x = h0; *(__half2*)&pk.y = h1;
            *(uint2*)(sW + r * NSTR + c) = pk;
        }
        __syncthreads();

        float acc[16][4];
        #pragma unroll
        for (int t = 0; t < 16; ++t)
            #pragma unroll
            for (int j = 0; j < 4; ++j) acc[t][j] = 0.f;

        #pragma unroll
        for (int kc = 0; kc < 8; ++kc) {
            int k0 = kc * 16;
            unsigned a0, a1, a2, a3;
            {
                int r = row0 + (lane & 15);
                int c = k0 + 8 * (lane >> 4);
                ldsm_x4(smem_u32(sX + r * NSTR + c), a0, a1, a2, a3);
            }
            #pragma unroll
            for (int nt = 0; nt < 8; ++nt) {
                int nn = nt * 16;
                unsigned b0, b1, b2, b3;
                int r = k0 + (lane & 15);
                int c = nn + 8 * (lane >> 4);
                ldsm_x4_t(smem_u32(sW + r * NSTR + c), b0, b1, b2, b3);
                mma16816(acc[2 * nt],     a0, a1, a2, a3, b0, b1);
                mma16816(acc[2 * nt + 1], a0, a1, a2, a3, b2, b3);
            }
        }
        __syncthreads();                   // done reading sW -> reuse as staging

        const float* bias = Bs[p];
        #pragma unroll
        for (int t = 0; t < 16; ++t) {
            int c = t * 8 + dc;
            float b0v = bias[c], b1v = bias[c + 1];
            __half2 lo = __floats2half2_rn(acc[t][0] + b0v, acc[t][1] + b1v);
            __half2 hi = __floats2half2_rn(acc[t][2] + b0v, acc[t][3] + b1v);
            *(__half2*)(sW + (row0 + dr) * NSTR + c)     = lo;
            *(__half2*)(sW + (row0 + dr + 8) * NSTR + c) = hi;
        }
        __syncwarp();

        __half* O = Os[p];
        for (int i = lane; i < 16 * 16; i += 32) {     // 16 rows x 16 uint4
            int r = i >> 4, ch = i & 15;
            int node = n0 + row0 + r;
            if (node < N_NODES)
                *(uint4*)(O + node * HC + ch * 8) =
                    *(uint4*)(sW + (row0 + r) * NSTR + ch * 8);
        }
    }
}

// ----------------------------- E1: edge GEMM ----------------------------------
// e = edge_attr @ We (HMMA, K padded 44->48), fp16 output in EDGE order
// (fully sequential 256B-per-row stores).
#define ASTR 72
#define WSTR 136
__global__ void __launch_bounds__(256, 2)
edge_gemm_kernel(const float* __restrict__ edge_attr,
                 const float* __restrict__ We)
{
    extern __shared__ __half smh[];
    __half* sA  = smh;                         // 128 x ASTR  (K in cols 0..47)
    __half* sWe = smh + 128 * ASTR;            // 48 x WSTR
    __half* sE  = sWe + 48 * WSTR;             // 128 x WSTR
    const int tid = threadIdx.x;
    const int warp = tid >> 5, lane = tid & 31;
    const int e0 = blockIdx.x * 128;           // E divisible by 128

    for (int i = tid; i < 128 * ED; i += 256) {
        int r = i / ED, c = i - r * ED;
        sA[r * ASTR + c] = __float2half(edge_attr[(e0 + r) * ED + c]);
    }
    for (int i = tid; i < 128 * 4; i += 256) { // zero K pad cols 44..47
        int r = i >> 2, c = 44 + (i & 3);
        sA[r * ASTR + c] = __float2half(0.f);
    }
    for (int i = tid; i < ED * 128; i += 256) {
        int r = i >> 7, c = i & 127;
        sWe[r * WSTR + c] = __float2half(We[i]);
    }
    for (int i = tid; i < 4 * 128; i += 256) { // zero K pad rows 44..47
        int r = 44 + (i >> 7), c = i & 127;
        sWe[r * WSTR + c] = __float2half(0.f);
    }
    __syncthreads();

    const int row0 = warp * 16;
    const int dr = lane >> 2;
    const int dc = 2 * (lane & 3);

    float acc[16][4];
    #pragma unroll
    for (int t = 0; t < 16; ++t)
        #pragma unroll
        for (int j = 0; j < 4; ++j) acc[t][j] = 0.f;

    #pragma unroll
    for (int kc = 0; kc < 3; ++kc) {
        int k0 = kc * 16;
        unsigned a0, a1, a2, a3;
        {
            int r = row0 + (lane & 15);
            int c = k0 + 8 * (lane >> 4);
            ldsm_x4(smem_u32(sA + r * ASTR + c), a0, a1, a2, a3);
        }
        #pragma unroll
        for (int nt = 0; nt < 8; ++nt) {
            int nn = nt * 16;
            unsigned b0, b1, b2, b3;
            int r = k0 + (lane & 15);
            int c = nn + 8 * (lane >> 4);
            ldsm_x4_t(smem_u32(sWe + r * WSTR + c), b0, b1, b2, b3);
            mma16816(acc[2 * nt],     a0, a1, a2, a3, b0, b1);
            mma16816(acc[2 * nt + 1], a0, a1, a2, a3, b2, b3);
        }
    }

    // stage fp16 tile (own rows only), then sequential global stores
    #pragma unroll
    for (int t = 0; t < 16; ++t) {
        int c = t * 8 + dc;
        *(__half2*)(sE + (row0 + dr) * WSTR + c) =
            __floats2half2_rn(acc[t][0], acc[t][1]);
        *(__half2*)(sE + (row0 + dr + 8) * WSTR + c) =
            __floats2half2_rn(acc[t][2], acc[t][3]);
    }
    __syncwarp();

    for (int i = lane; i < 16 * 16; i += 32) {     // 16 rows x 16 uint4
        int r = i >> 4, ch = i & 15;
        *(uint4*)(g_e + (e0 + row0 + r) * HC + ch * 8) =
            *(uint4*)(sE + (row0 + r) * WSTR + ch * 8);
    }
}

// ----------------------------- E2: fused gather + softmax + aggregate ---------
// One warp per dst node; lane l owns cols 4l..4l+3 (head h=l>>3).
// q[dst] loaded once; per edge: gather k[src], v[src], e[edge]; paired online
// softmax (one rescale per 2 edges) accumulated in registers.
__global__ void __launch_bounds__(256, 8)
agg_fused_kernel(const void* __restrict__ ei, float* __restrict__ out)
{
    const int n = (blockIdx.x * blockDim.x + threadIdx.x) >> 5; // exactly N warps
    const int l = threadIdx.x & 31;
    const int c0 = 4 * l;
    const int is64 = g_is64;
    const float isc = 0.17677669529663689f;    // 1/sqrt(32)

    const int beg = g_off[n], end = g_off[n + 1];

    uint2 qr = *(const uint2*)(g_qh + n * HC + c0);
    float2 q01 = __half22float2(*(__half2*)&qr.x);
    float2 q23 = __half22float2(*(__half2*)&qr.y);

    float m = -1e30f, den = 0.f;
    float acc0 = 0.f, acc1 = 0.f, acc2 = 0.f, acc3 = 0.f;

    for (int i = beg; i < end; i += 2) {
        const bool has2 = (i + 1 < end);
        int ea = g_elist[i];
        int eb = has2 ? g_elist[i + 1] : ea;
        int sa = ld_src(ei, ea, is64);
        int sb = ld_src(ei, eb, is64);
        sa = min(max(sa, 0), N_NODES - 1);
        sb = min(max(sb, 0), N_NODES - 1);

        // issue all 6 gathers before consuming
        uint2 er_a = *(const uint2*)(g_e  + ea * HC + c0);
        uint2 kr_a = *(const uint2*)(g_kh + sa * HC + c0);
        uint2 vr_a = *(const uint2*)(g_vh + sa * HC + c0);
        uint2 er_b = *(const uint2*)(g_e  + eb * HC + c0);
        uint2 kr_b = *(const uint2*)(g_kh + sb * HC + c0);
        uint2 vr_b = *(const uint2*)(g_vh + sb * HC + c0);

        float2 ea01 = __half22float2(*(__half2*)&er_a.x);
        float2 ea23 = __half22float2(*(__half2*)&er_a.y);
        float2 ka01 = __half22float2(*(__half2*)&kr_a.x);
        float2 ka23 = __half22float2(*(__half2*)&kr_a.y);
        float2 va01 = __half22float2(*(__half2*)&vr_a.x);
        float2 va23 = __half22float2(*(__half2*)&vr_a.y);
        float2 eb01 = __half22float2(*(__half2*)&er_b.x);
        float2 eb23 = __half22float2(*(__half2*)&er_b.y);
        float2 kb01 = __half22float2(*(__half2*)&kr_b.x);
        float2 kb23 = __half22float2(*(__half2*)&kr_b.y);
        float2 vb01 = __half22float2(*(__half2*)&vr_b.x);
        float2 vb23 = __half22float2(*(__half2*)&vr_b.y);

        float pa = q01.x * (ka01.x + ea01.x) + q01.y * (ka01.y + ea01.y)
                 + q23.x * (ka23.x + ea23.x) + q23.y * (ka23.y + ea23.y);
        float pb = q01.x * (kb01.x + eb01.x) + q01.y * (kb01.y + eb01.y)
                 + q23.x * (kb23.x + eb23.x) + q23.y * (kb23.y + eb23.y);

        pa += __shfl_xor_sync(0xffffffffu, pa, 1);
        pb += __shfl_xor_sync(0xffffffffu, pb, 1);
        pa += __shfl_xor_sync(0xffffffffu, pa, 2);
        pb += __shfl_xor_sync(0xffffffffu, pb, 2);
        pa += __shfl_xor_sync(0xffffffffu, pa, 4);
        pb += __shfl_xor_sync(0xffffffffu, pb, 4);

        float aa = pa * isc;
        float ab = has2 ? (pb * isc) : -1e30f;

        float nm = fmaxf(m, fmaxf(aa, ab));
        float sc = __expf(m - nm);
        float wa = __expf(aa - nm);
        float wb = __expf(ab - nm);           // 0 when !has2
        den = den * sc + wa + wb;
        acc0 = acc0 * sc + wa * (va01.x + ea01.x) + wb * (vb01.x + eb01.x);
        acc1 = acc1 * sc + wa * (va01.y + ea01.y) + wb * (vb01.y + eb01.y);
        acc2 = acc2 * sc + wa * (va23.x + ea23.x) + wb * (vb23.x + eb23.x);
        acc3 = acc3 * sc + wa * (va23.y + ea23.y) + wb * (vb23.y + eb23.y);
        m = nm;
    }

    float inv = 1.f / (den + 1e-16f);
    uint2 skr = *(const uint2*)(g_skip + n * HC + c0);
    float2 s01 = __half22float2(*(__half2*)&skr.x);
    float2 s23 = __half22float2(*(__half2*)&skr.y);
    *(float4*)(out + n * HC + c0) =
        make_float4(acc0 * inv + s01.x, acc1 * inv + s01.y,
                    acc2 * inv + s23.x, acc3 * inv + s23.y);
}

// ----------------------------- launch -----------------------------------------
extern "C" void kernel_launch(void* const* d_in, const int* in_sizes, int n_in,
                              void* d_out, int out_size)
{
    const float* x   = (const float*)d_in[0];
    const void*  ei  = d_in[1];
    const float* ea  = (const float*)d_in[2];
    const float* Wq  = (const float*)d_in[3];
    const float* bq  = (const float*)d_in[4];
    const float* Wk  = (const float*)d_in[5];
    const float* bk  = (const float*)d_in[6];
    const float* Wv  = (const float*)d_in[7];
    const float* bv  = (const float*)d_in[8];
    const float* We  = (const float*)d_in[9];
    const float* Wsk = (const float*)d_in[10];
    const float* bsk = (const float*)d_in[11];
    float* out = (float*)d_out;

    const int smem_node = 2 * 128 * NSTR * 2;                       // 69.6 KB
    const int smem_edge = (128 * ASTR + 48 * WSTR + 128 * WSTR) * 2; // 66.3 KB
    cudaFuncSetAttribute(node_proj_kernel,
                         cudaFuncAttributeMaxDynamicSharedMemorySize, smem_node);
    cudaFuncSetAttribute(edge_gemm_kernel,
                         cudaFuncAttributeMaxDynamicSharedMemorySize, smem_edge);

    detect_kernel<<<1, 256>>>((const int*)ei);
    zero_counts_kernel<<<(N_NODES + 255) / 256, 256>>>();
    count_kernel<<<E_EDGES / 256, 256>>>(ei);
    scan1_kernel<<<SCAN_B, 256>>>();
    scan2_kernel<<<1, 256>>>();
    scan3_kernel<<<SCAN_B, 256>>>();
    fill_kernel<<<E_EDGES / 256, 256>>>(ei);

    node_proj_kernel<<<(N_NODES + 127) / 128, 256, smem_node>>>(
        x, Wq, bq, Wk, bk, Wv, bv, Wsk, bsk);
    edge_gemm_kernel<<<E_EDGES / 128, 256, smem_edge>>>(ea, We);
    agg_fused_kernel<<<(N_NODES * 32) / 256, 256>>>(ei, out);
}